// round 13
// baseline (speedup 1.0000x reference)
#include <cuda_runtime.h>
#include <cuda_bf16.h>
#include <math.h>
#include <stdint.h>

#define B_ 4
#define S_ 2048
#define C_ 512
#define H_ 8
#define D_ 64
#define NTOK (B_ * S_)
#define ATT_SCALE 0.125f
#define LN_EPS 1e-5f
#define NC ((size_t)NTOK * C_)
#define CC ((size_t)C_ * C_)

// ---------------------------------------------------------------------------
// Scratch buffers
// ---------------------------------------------------------------------------
__device__ float g_t0 [NC];
__device__ float g_xln[NC];
__device__ float g_t1 [NC];

__device__ uint16_t g_xhi [NC],     g_xlo [NC];
__device__ uint16_t g_whi [6 * CC], g_wlo [6 * CC];
__device__ uint16_t g_qkvhi[3 * NC], g_qkvlo[3 * NC];
__device__ uint16_t g_atthi[NC],    g_attlo[NC];
__device__ uint16_t g_t0hi[NC],     g_t0lo[NC];

// ---------------------------------------------------------------------------
// Helpers
// ---------------------------------------------------------------------------
__device__ __forceinline__ uint32_t smem_u32(const void* p) {
    uint32_t a;
    asm("{ .reg .u64 t; cvta.to.shared.u64 t, %1; cvt.u32.u64 %0, t; }"
        : "=r"(a) : "l"(p));
    return a;
}
__device__ __forceinline__ void ldsm4(uint32_t* r, uint32_t addr) {
    asm volatile("ldmatrix.sync.aligned.m8n8.x4.shared.b16 {%0,%1,%2,%3}, [%4];"
                 : "=r"(r[0]), "=r"(r[1]), "=r"(r[2]), "=r"(r[3]) : "r"(addr));
}
__device__ __forceinline__ void ldsm4t(uint32_t* r, uint32_t addr) {
    asm volatile("ldmatrix.sync.aligned.m8n8.x4.trans.shared.b16 {%0,%1,%2,%3}, [%4];"
                 : "=r"(r[0]), "=r"(r[1]), "=r"(r[2]), "=r"(r[3]) : "r"(addr));
}
__device__ __forceinline__ void mma16816(float* c, const uint32_t* a, const uint32_t* b) {
    asm volatile(
        "mma.sync.aligned.m16n8k16.row.col.f32.bf16.bf16.f32 "
        "{%0,%1,%2,%3},{%4,%5,%6,%7},{%8,%9},{%0,%1,%2,%3};"
        : "+f"(c[0]), "+f"(c[1]), "+f"(c[2]), "+f"(c[3])
        : "r"(a[0]), "r"(a[1]), "r"(a[2]), "r"(a[3]), "r"(b[0]), "r"(b[1]));
}
__device__ __forceinline__ void cpa16(uint32_t dst, const void* src) {
    asm volatile("cp.async.cg.shared.global [%0], [%1], 16;" :: "r"(dst), "l"(src));
}
#define CPA_COMMIT() asm volatile("cp.async.commit_group;")
#define CPA_WAIT0()  asm volatile("cp.async.wait_group 0;")
#define CPA_WAIT1()  asm volatile("cp.async.wait_group 1;")

__device__ __forceinline__ uint16_t f2bf(float x) {
    __nv_bfloat16 b = __float2bfloat16(x);
    return *(uint16_t*)&b;
}
__device__ __forceinline__ float bf2f(uint16_t u) {
    __nv_bfloat16 b = *(__nv_bfloat16*)&u;
    return __bfloat162float(b);
}
__device__ __forceinline__ void split2(float x0, float x1, uint32_t& hi, uint32_t& lo) {
    uint16_t h0 = f2bf(x0), h1 = f2bf(x1);
    uint16_t l0 = f2bf(x0 - bf2f(h0)), l1 = f2bf(x1 - bf2f(h1));
    hi = (uint32_t)h0 | ((uint32_t)h1 << 16);
    lo = (uint32_t)l0 | ((uint32_t)l1 << 16);
}

// ---------------------------------------------------------------------------
// Split kernels
// ---------------------------------------------------------------------------
__global__ __launch_bounds__(256) void split1_k(
    const float* __restrict__ in, uint16_t* __restrict__ hi,
    uint16_t* __restrict__ lo)
{
    const size_t i = ((size_t)blockIdx.x * 256 + threadIdx.x) * 8;
    float4 a = *(const float4*)(in + i);
    float4 b = *(const float4*)(in + i + 4);
    uint32_t h0, l0, h1, l1, h2, l2, h3, l3;
    split2(a.x, a.y, h0, l0); split2(a.z, a.w, h1, l1);
    split2(b.x, b.y, h2, l2); split2(b.z, b.w, h3, l3);
    *(uint4*)(hi + i) = make_uint4(h0, h1, h2, h3);
    *(uint4*)(lo + i) = make_uint4(l0, l1, l2, l3);
}

__global__ __launch_bounds__(256) void splitw_k(
    const float* __restrict__ w0, const float* __restrict__ w1,
    const float* __restrict__ w2, const float* __restrict__ w3,
    const float* __restrict__ w4, const float* __restrict__ w5,
    uint16_t* __restrict__ hi, uint16_t* __restrict__ lo)
{
    const int z = blockIdx.z;
    const float* w = (z == 0) ? w0 : (z == 1) ? w1 : (z == 2) ? w2 :
                     (z == 3) ? w3 : (z == 4) ? w4 : w5;
    const size_t j = ((size_t)blockIdx.x * 256 + threadIdx.x) * 8;
    const size_t o = (size_t)z * CC + j;
    float4 a = *(const float4*)(w + j);
    float4 b = *(const float4*)(w + j + 4);
    uint32_t h0, l0, h1, l1, h2, l2, h3, l3;
    split2(a.x, a.y, h0, l0); split2(a.z, a.w, h1, l1);
    split2(b.x, b.y, h2, l2); split2(b.z, b.w, h3, l3);
    *(uint4*)(hi + o) = make_uint4(h0, h1, h2, h3);
    *(uint4*)(lo + o) = make_uint4(l0, l1, l2, l3);
}

// ---------------------------------------------------------------------------
// bf16x3 GEMM: 128x128 tile, BK=64, 256 threads, 3-stage cp.async ring,
// one __syncthreads per chunk (8 chunks).
// ---------------------------------------------------------------------------
#define GSA 72                    // A row stride (64 k + 8 pad) bf16
#define GSB 136                   // B row stride (128 n + 8 pad) bf16
#define APL 18432                 // 128 * 72 * 2
#define BPL 17408                 // 64 * 136 * 2
#define STG (2 * APL + 2 * BPL)   // 71680
#define GEMM_SMEM (3 * STG)       // 215040

__global__ __launch_bounds__(256) void gemm_tc(
    const uint16_t* __restrict__ Ahi, const uint16_t* __restrict__ Alo,
    const uint16_t* __restrict__ Whi, const uint16_t* __restrict__ Wlo,
    float* __restrict__ Cf, const float* __restrict__ bias,
    uint16_t* __restrict__ Chi, uint16_t* __restrict__ Clo)
{
    extern __shared__ char sm[];
    const uint32_t smb = smem_u32(sm);
    const int tid = threadIdx.x;
    const int wid = tid >> 5, lane = tid & 31;
    const int g = lane >> 2, tig = lane & 3;
    const int wm = wid >> 2, wn = wid & 3;
    const int n0 = blockIdx.x * 128, m0 = blockIdx.y * 128;
    const uint16_t* Wh = Whi + (size_t)blockIdx.z * CC;
    const uint16_t* Wl = Wlo + (size_t)blockIdx.z * CC;
    const size_t zO = (size_t)blockIdx.z * NC;

    float c[4][4][4];
#pragma unroll
    for (int i = 0; i < 4; i++)
#pragma unroll
        for (int j = 0; j < 4; j++)
#pragma unroll
            for (int e = 0; e < 4; e++) c[i][j][e] = 0.f;

    auto preload = [&](int chunk, int buf) {
        const uint32_t sb = smb + (uint32_t)buf * STG;
        const int k0 = chunk * 64;
        // A planes: 128 rows x 64 k = 1024 16B-chunks per plane
#pragma unroll
        for (int rep = 0; rep < 4; rep++) {
            const int cc = tid + rep * 256;
            const int row = cc >> 3, kc = cc & 7;
            const uint32_t d = sb + row * 144 + kc * 16;
            const size_t so = (size_t)(m0 + row) * C_ + k0 + kc * 8;
            cpa16(d, Ahi + so);
            cpa16(d + APL, Alo + so);
        }
        // B planes: 64 k-rows x 128 n = 1024 16B-chunks per plane
#pragma unroll
        for (int rep = 0; rep < 4; rep++) {
            const int cc = tid + rep * 256;
            const int row = cc >> 4, nc = cc & 15;
            const uint32_t d = sb + 2 * APL + row * 272 + nc * 16;
            const size_t so = (size_t)(k0 + row) * C_ + n0 + nc * 8;
            cpa16(d, Wh + so);
            cpa16(d + BPL, Wl + so);
        }
    };

    auto compute = [&](int buf) {
        const uint32_t sb = smb + (uint32_t)buf * STG;
#pragma unroll
        for (int kk = 0; kk < 64; kk += 16) {
            uint32_t ah[4][4], al[4][4];
#pragma unroll
            for (int mf = 0; mf < 4; mf++) {
                const uint32_t ae =
                    (uint32_t)((wm * 64 + mf * 16 + (lane & 15)) * GSA +
                               kk + ((lane >> 4) << 3)) * 2;
                ldsm4(ah[mf], sb + ae);
                ldsm4(al[mf], sb + APL + ae);
            }
            uint32_t bh[4][2], bl[4][2];
#pragma unroll
            for (int nfp = 0; nfp < 2; nfp++) {
                const uint32_t be =
                    (uint32_t)((kk + (lane & 7) + (((lane >> 3) & 1) << 3)) * GSB +
                               wn * 32 + nfp * 16 + ((lane >> 4) << 3)) * 2;
                uint32_t r[4];
                ldsm4t(r, sb + 2 * APL + be);
                bh[nfp * 2][0] = r[0]; bh[nfp * 2][1] = r[1];
                bh[nfp * 2 + 1][0] = r[2]; bh[nfp * 2 + 1][1] = r[3];
                ldsm4t(r, sb + 2 * APL + BPL + be);
                bl[nfp * 2][0] = r[0]; bl[nfp * 2][1] = r[1];
                bl[nfp * 2 + 1][0] = r[2]; bl[nfp * 2 + 1][1] = r[3];
            }
#pragma unroll
            for (int mf = 0; mf < 4; mf++)
#pragma unroll
                for (int nf = 0; nf < 4; nf++) {
                    mma16816(c[mf][nf], ah[mf], bh[nf]);
                    mma16816(c[mf][nf], ah[mf], bl[nf]);
                    mma16816(c[mf][nf], al[mf], bh[nf]);
                }
        }
    };

    // 3-stage ring, 8 chunks, one sync per chunk.
    preload(0, 0);
    CPA_COMMIT();
    preload(1, 1);
    CPA_COMMIT();
    for (int ch = 0; ch < 8; ch++) {
        if (ch < 7) CPA_WAIT1(); else CPA_WAIT0();
        __syncthreads();
        if (ch + 2 < 8) {
            preload(ch + 2, (ch + 2) % 3);
            CPA_COMMIT();
        }
        compute(ch % 3);
    }

#pragma unroll
    for (int mf = 0; mf < 4; mf++) {
        const int row0 = m0 + wm * 64 + mf * 16 + g;
        const int row1 = row0 + 8;
#pragma unroll
        for (int nf = 0; nf < 4; nf++) {
            const int col = n0 + wn * 32 + nf * 8 + tig * 2;
            if (Cf) {
                float bx = 0.f, by = 0.f;
                if (bias) { bx = bias[col]; by = bias[col + 1]; }
                *(float2*)(Cf + (size_t)row0 * C_ + col) =
                    make_float2(c[mf][nf][0] + bx, c[mf][nf][1] + by);
                *(float2*)(Cf + (size_t)row1 * C_ + col) =
                    make_float2(c[mf][nf][2] + bx, c[mf][nf][3] + by);
            } else {
                uint32_t hi, lo;
                split2(c[mf][nf][0], c[mf][nf][1], hi, lo);
                *(uint32_t*)(Chi + zO + (size_t)row0 * C_ + col) = hi;
                *(uint32_t*)(Clo + zO + (size_t)row0 * C_ + col) = lo;
                split2(c[mf][nf][2], c[mf][nf][3], hi, lo);
                *(uint32_t*)(Chi + zO + (size_t)row1 * C_ + col) = hi;
                *(uint32_t*)(Clo + zO + (size_t)row1 * C_ + col) = lo;
            }
        }
    }
}

// ---------------------------------------------------------------------------
// LayerNorm
// ---------------------------------------------------------------------------
__device__ __forceinline__ void ln_row_stats(float4 v, int t, float& mean,
                                             float& inv, float* rs, float* rs2)
{
    float s  = v.x + v.y + v.z + v.w;
    float s2 = v.x * v.x + v.y * v.y + v.z * v.z + v.w * v.w;
#pragma unroll
    for (int o = 16; o; o >>= 1) {
        s  += __shfl_xor_sync(0xffffffffu, s,  o);
        s2 += __shfl_xor_sync(0xffffffffu, s2, o);
    }
    const int wid = t >> 5;
    if ((t & 31) == 0) { rs[wid] = s; rs2[wid] = s2; }
    __syncthreads();
    float S  = rs[0]  + rs[1]  + rs[2]  + rs[3];
    float S2 = rs2[0] + rs2[1] + rs2[2] + rs2[3];
    mean = S * (1.f / C_);
    const float var = S2 * (1.f / C_) - mean * mean;
    inv = rsqrtf(var + LN_EPS);
}

__global__ __launch_bounds__(128) void ln_k(
    const float* __restrict__ in, const float* __restrict__ res,
    const float* __restrict__ w, const float* __restrict__ b,
    float* __restrict__ out, uint16_t* __restrict__ ohi,
    uint16_t* __restrict__ olo)
{
    const int row = blockIdx.x;
    const int t = threadIdx.x;
    __shared__ float rs[4], rs2[4];

    float4 v = *(const float4*)(in + (size_t)row * C_ + t * 4);
    if (res) {
        float4 r = *(const float4*)(res + (size_t)row * C_ + t * 4);
        v.x += r.x; v.y += r.y; v.z += r.z; v.w += r.w;
    }
    float mean, inv;
    ln_row_stats(v, t, mean, inv, rs, rs2);

    float4 wv = *(const float4*)(w + t * 4);
    float4 bv = *(const float4*)(b + t * 4);
    float4 o;
    o.x = (v.x - mean) * inv * wv.x + bv.x;
    o.y = (v.y - mean) * inv * wv.y + bv.y;
    o.z = (v.z - mean) * inv * wv.z + bv.z;
    o.w = (v.w - mean) * inv * wv.w + bv.w;
    if (out)
        *(float4*)(out + (size_t)row * C_ + t * 4) = o;
    if (ohi) {
        uint32_t h0, l0, h1, l1;
        split2(o.x, o.y, h0, l0);
        split2(o.z, o.w, h1, l1);
        *(uint2*)(ohi + (size_t)row * C_ + t * 4) = make_uint2(h0, h1);
        *(uint2*)(olo + (size_t)row * C_ + t * 4) = make_uint2(l0, l1);
    }
}

// Fused double-LN: xln = LN1(in+res); split = LN2(xln).
__global__ __launch_bounds__(128) void ln2x_k(
    const float* __restrict__ in, const float* __restrict__ res,
    const float* __restrict__ w1, const float* __restrict__ b1,
    float* __restrict__ xln_out,
    const float* __restrict__ w2, const float* __restrict__ b2,
    uint16_t* __restrict__ ohi, uint16_t* __restrict__ olo)
{
    const int row = blockIdx.x;
    const int t = threadIdx.x;
    __shared__ float rs[4], rs2[4];

    float4 v = *(const float4*)(in + (size_t)row * C_ + t * 4);
    float4 r = *(const float4*)(res + (size_t)row * C_ + t * 4);
    v.x += r.x; v.y += r.y; v.z += r.z; v.w += r.w;

    float mean, inv;
    ln_row_stats(v, t, mean, inv, rs, rs2);

    float4 w1v = *(const float4*)(w1 + t * 4);
    float4 b1v = *(const float4*)(b1 + t * 4);
    float4 x1;
    x1.x = (v.x - mean) * inv * w1v.x + b1v.x;
    x1.y = (v.y - mean) * inv * w1v.y + b1v.y;
    x1.z = (v.z - mean) * inv * w1v.z + b1v.z;
    x1.w = (v.w - mean) * inv * w1v.w + b1v.w;
    *(float4*)(xln_out + (size_t)row * C_ + t * 4) = x1;

    __syncthreads();
    float mean2, inv2;
    ln_row_stats(x1, t, mean2, inv2, rs, rs2);

    float4 w2v = *(const float4*)(w2 + t * 4);
    float4 b2v = *(const float4*)(b2 + t * 4);
    float4 o;
    o.x = (x1.x - mean2) * inv2 * w2v.x + b2v.x;
    o.y = (x1.y - mean2) * inv2 * w2v.y + b2v.y;
    o.z = (x1.z - mean2) * inv2 * w2v.z + b2v.z;
    o.w = (x1.w - mean2) * inv2 * w2v.w + b2v.w;
    uint32_t h0, l0, h1, l1;
    split2(o.x, o.y, h0, l0);
    split2(o.z, o.w, h1, l1);
    *(uint2*)(ohi + (size_t)row * C_ + t * 4) = make_uint2(h0, h1);
    *(uint2*)(olo + (size_t)row * C_ + t * 4) = make_uint2(l0, l1);
}

// ---------------------------------------------------------------------------
// FA2-style flash attention (R5/R12 proven version, unchanged).
// ---------------------------------------------------------------------------
#define FS 72
#define PLANE 9216
#define BUFSZ (4 * PLANE)
#define FLASH_SMEM (2 * BUFSZ)

__global__ __launch_bounds__(256, 1) void flash_k(
    const uint16_t* __restrict__ QKVhi, const uint16_t* __restrict__ QKVlo,
    uint16_t* __restrict__ Ohi, uint16_t* __restrict__ Olo)
{
    extern __shared__ char sm[];
    const uint32_t smb = smem_u32(sm);

    const int tid = threadIdx.x;
    const int wid = tid >> 5, lane = tid & 31;
    const int g = lane >> 2, tig = lane & 3;

    const int qt = (gridDim.x - 1) - blockIdx.x;
    const int bh = blockIdx.y;
    const int b  = bh >> 3, h = bh & 7;
    const size_t base = (size_t)b * S_ * C_ + (size_t)h * D_;
    const int q0 = qt * 128;
    const int wr0 = wid * 16;

    const uint16_t* Qhi = QKVhi + base;
    const uint16_t* Qlo = QKVlo + base;
    const uint16_t* Khi = QKVhi + NC + base;
    const uint16_t* Klo = QKVlo + NC + base;
    const uint16_t* Vhi = QKVhi + 2 * NC + base;
    const uint16_t* Vlo = QKVlo + 2 * NC + base;

#pragma unroll
    for (int p = 0; p < 8; p++) {
        const int id = p * 256 + tid;
        const int half = id >> 10;
        const int pl = (id >> 9) & 1;
        const int rl = (id & 511) >> 3;
        const int ch = id & 7;
        const uint32_t dst = smb + (half * 2 + pl) * PLANE +
                             (uint32_t)(rl * FS + ch * 8) * 2;
        const uint16_t* src = (pl ? Qlo : Qhi) +
                              (size_t)(q0 + half * 64 + rl) * C_ + ch * 8;
        cpa16(dst, src);
    }
    CPA_COMMIT();
    CPA_WAIT0();
    __syncthreads();

    uint32_t qh[4][4], ql[4][4];
    {
        const uint32_t areaH = smb + ((wid >= 4) ? 2 * PLANE : 0);
        const int lw = (wid & 3) * 16;
#pragma unroll
        for (int kf = 0; kf < 4; kf++) {
            const uint32_t ae =
                (uint32_t)((lw + (lane & 15)) * FS + kf * 16 +
                           ((lane >> 4) << 3)) * 2;
            ldsm4(qh[kf], areaH + ae);
            ldsm4(ql[kf], areaH + PLANE + ae);
        }
    }
    __syncthreads();

    float acc[8][4];
#pragma unroll
    for (int i = 0; i < 8; i++)
#pragma unroll
        for (int e = 0; e < 4; e++) acc[i][e] = 0.f;
    float m0 = -1e30f, m1 = -1e30f, l0 = 0.f, l1 = 0.f;

    const int r0 = q0 + wr0 + g;
    const int r1 = r0 + 8;
    const int nkt = 2 * qt + 2;

    auto preload = [&](int kt, int buf) {
        const int k0 = kt * 64;
        const uint32_t bb = smb + buf * BUFSZ;
#pragma unroll
        for (int p = 0; p < 8; p++) {
            const int id = p * 256 + tid;
            const int pl = id >> 9;
            const int rl = (id & 511) >> 3;
            const int ch = id & 7;
            const uint32_t dst = bb + pl * PLANE +
                                 (uint32_t)(rl * FS + ch * 8) * 2;
            const uint16_t* src =
                ((pl == 0) ? Khi : (pl == 1) ? Klo : (pl == 2) ? Vhi : Vlo) +
                (size_t)(k0 + rl) * C_ + ch * 8;
            cpa16(dst, src);
        }
    };

    preload(0, 0);
    CPA_COMMIT();

    for (int kt = 0; kt < nkt; kt++) {
        const int k0g = kt * 64;
        CPA_WAIT0();
        __syncthreads();
        if (kt + 1 < nkt) {
            preload(kt + 1, (kt + 1) & 1);
            CPA_COMMIT();
        }

        if (k0g <= q0 + wr0 + 15) {
            const uint32_t kb = smb + (kt & 1) * BUFSZ;

            float s[8][4];
#pragma unroll
            for (int i = 0; i < 8; i++)
#pragma unroll
                for (int e = 0; e < 4; e++) s[i][e] = 0.f;

#pragma unroll
            for (int kf = 0; kf < 4; kf++) {
#pragma unroll
                for (int nfq = 0; nfq < 4; nfq++) {
                    const uint32_t be =
                        (uint32_t)((nfq * 16 + (lane & 7) + ((lane >> 4) << 3)) * FS +
                                   kf * 16 + (((lane >> 3) & 1) << 3)) * 2;
                    uint32_t rh[4], rl_[4];
                    ldsm4(rh, kb + be);
                    ldsm4(rl_, kb + PLANE + be);
                    mma16816(s[2 * nfq], qh[kf], rh);
                    mma16816(s[2 * nfq], qh[kf], rl_);
                    mma16816(s[2 * nfq], ql[kf], rh);
                    mma16816(s[2 * nfq + 1], qh[kf], rh + 2);
                    mma16816(s[2 * nfq + 1], qh[kf], rl_ + 2);
                    mma16816(s[2 * nfq + 1], ql[kf], rh + 2);
                }
            }

            const bool needmask = (k0g + 63 > q0 + wr0);
#pragma unroll
            for (int nf = 0; nf < 8; nf++) {
#pragma unroll
                for (int e = 0; e < 4; e++) s[nf][e] *= ATT_SCALE;
                if (needmask) {
                    const int cc = k0g + nf * 8 + tig * 2;
                    if (cc     > r0) s[nf][0] = -1e30f;
                    if (cc + 1 > r0) s[nf][1] = -1e30f;
                    if (cc     > r1) s[nf][2] = -1e30f;
                    if (cc + 1 > r1) s[nf][3] = -1e30f;
                }
            }

            float ml0 = -1e30f, ml1 = -1e30f;
#pragma unroll
            for (int nf = 0; nf < 8; nf++) {
                ml0 = fmaxf(ml0, fmaxf(s[nf][0], s[nf][1]));
                ml1 = fmaxf(ml1, fmaxf(s[nf][2], s[nf][3]));
            }
            ml0 = fmaxf(ml0, __shfl_xor_sync(0xffffffffu, ml0, 1));
            ml0 = fmaxf(ml0, __shfl_xor_sync(0xffffffffu, ml0, 2));
            ml1 = fmaxf(ml1, __shfl_xor_sync(0xffffffffu, ml1, 1));
            ml1 = fmaxf(ml1, __shfl_xor_sync(0xffffffffu, ml1, 2));

            const float mn0 = fmaxf(m0, ml0);
            const float mn1 = fmaxf(m1, ml1);
            const float cr0 = __expf(m0 - mn0);
            const float cr1 = __expf(m1 - mn1);
            m0 = mn0; m1 = mn1;

            float rs0 = 0.f, rs1 = 0.f;
#pragma unroll
            for (int nf = 0; nf < 8; nf++) {
                s[nf][0] = __expf(s[nf][0] - mn0);
                s[nf][1] = __expf(s[nf][1] - mn0);
                s[nf][2] = __expf(s[nf][2] - mn1);
                s[nf][3] = __expf(s[nf][3] - mn1);
                rs0 += s[nf][0] + s[nf][1];
                rs1 += s[nf][2] + s[nf][3];
                acc[nf][0] *= cr0; acc[nf][1] *= cr0;
                acc[nf][2] *= cr1; acc[nf][3] *= cr1;
            }
            rs0 += __shfl_xor_sync(0xffffffffu, rs0, 1);
            rs0 += __shfl_xor_sync(0xffffffffu, rs0, 2);
            rs1 += __shfl_xor_sync(0xffffffffu, rs1, 1);
            rs1 += __shfl_xor_sync(0xffffffffu, rs1, 2);
            l0 = l0 * cr0 + rs0;
            l1 = l1 * cr1 + rs1;

#pragma unroll
            for (int kf = 0; kf < 4; kf++) {
                uint32_t aph[4], apl[4];
                split2(s[2 * kf][0],     s[2 * kf][1],     aph[0], apl[0]);
                split2(s[2 * kf][2],     s[2 * kf][3],     aph[1], apl[1]);
                split2(s[2 * kf + 1][0], s[2 * kf + 1][1], aph[2], apl[2]);
                split2(s[2 * kf + 1][2], s[2 * kf + 1][3], aph[3], apl[3]);
#pragma unroll
                for (int nfq = 0; nfq < 4; nfq++) {
                    const uint32_t be =
                        (uint32_t)((kf * 16 + (lane & 7) + (((lane >> 3) & 1) << 3)) * FS +
                                   nfq * 16 + ((lane >> 4) << 3)) * 2;
                    uint32_t vh[4], vl[4];
                    ldsm4t(vh, kb + 2 * PLANE + be);
                    ldsm4t(vl, kb + 3 * PLANE + be);
                    mma16816(acc[2 * nfq], aph, vh);
                    mma16816(acc[2 * nfq], aph, vl);
                    mma16816(acc[2 * nfq], apl, vh);
                    mma16816(acc[2 * nfq + 1], aph, vh + 2);
                    mma16816(acc[2 * nfq + 1], aph, vl + 2);
                    mma16816(acc[2 * nfq + 1], apl, vh + 2);
                }
            }
        }
    }

    const float il0 = 1.f / l0;
    const float il1 = 1.f / l1;
#pragma unroll
    for (int nf = 0; nf < 8; nf++) {
        const int col = nf * 8 + tig * 2;
        uint32_t hi, lo;
        split2(acc[nf][0] * il0, acc[nf][1] * il0, hi, lo);
        *(uint32_t*)(Ohi + base + (size_t)r0 * C_ + col) = hi;
        *(uint32_t*)(Olo + base + (size_t)r0 * C_ + col) = lo;
        split2(acc[nf][2] * il1, acc[nf][3] * il1, hi, lo);
        *(uint32_t*)(Ohi + base + (size_t)r1 * C_ + col) = hi;
        *(uint32_t*)(Olo + base + (size_t)r1 * C_ + col) = lo;
    }
}

// ---------------------------------------------------------------------------
// Launcher
// ---------------------------------------------------------------------------
extern "C" void kernel_launch(void* const* d_in, const int* in_sizes, int n_in,
                              void* d_out, int out_size)
{
    (void)in_sizes; (void)n_in; (void)out_size;

    const float* x        = (const float*)d_in[0];
    const float* Wq       = (const float*)d_in[1];
    const float* Wk       = (const float*)d_in[2];
    const float* Wv       = (const float*)d_in[3];
    const float* Wo       = (const float*)d_in[4];
    const float* ln1_w    = (const float*)d_in[5];
    const float* ln1_b    = (const float*)d_in[6];
    const float* ff_ln1_w = (const float*)d_in[7];
    const float* ff_ln1_b = (const float*)d_in[8];
    const float* ff_w1    = (const float*)d_in[9];
    const float* ff_b1    = (const float*)d_in[10];
    const float* ff_ln2_w = (const float*)d_in[11];
    const float* ff_ln2_b = (const float*)d_in[12];
    const float* ff_w2    = (const float*)d_in[13];
    const float* ff_b2    = (const float*)d_in[14];
    const float* ln2_w    = (const float*)d_in[15];
    const float* ln2_b    = (const float*)d_in[16];
    float* out = (float*)d_out;

    float *t0, *xln, *t1;
    uint16_t *xhi, *xlo, *whi, *wlo, *qkvhi, *qkvlo, *atthi, *attlo, *t0hi, *t0lo;
    cudaGetSymbolAddress((void**)&t0,    g_t0);
    cudaGetSymbolAddress((void**)&xln,   g_xln);
    cudaGetSymbolAddress((void**)&t1,    g_t1);
    cudaGetSymbolAddress((void**)&xhi,   g_xhi);
    cudaGetSymbolAddress((void**)&xlo,   g_xlo);
    cudaGetSymbolAddress((void**)&whi,   g_whi);
    cudaGetSymbolAddress((void**)&wlo,   g_wlo);
    cudaGetSymbolAddress((void**)&qkvhi, g_qkvhi);
    cudaGetSymbolAddress((void**)&qkvlo, g_qkvlo);
    cudaGetSymbolAddress((void**)&atthi, g_atthi);
    cudaGetSymbolAddress((void**)&attlo, g_attlo);
    cudaGetSymbolAddress((void**)&t0hi,  g_t0hi);
    cudaGetSymbolAddress((void**)&t0lo,  g_t0lo);

    cudaFuncSetAttribute(flash_k, cudaFuncAttributeMaxDynamicSharedMemorySize,
                         FLASH_SMEM);
    cudaFuncSetAttribute(gemm_tc, cudaFuncAttributeMaxDynamicSharedMemorySize,
                         GEMM_SMEM);

    // Split inputs
    split1_k<<<(int)(NC / 2048), 256>>>(x, xhi, xlo);
    splitw_k<<<dim3((int)(CC / 2048), 1, 6), 256>>>(Wq, Wk, Wv, Wo, ff_w1, ff_w2,
                                                    whi, wlo);

    const dim3 g3(C_ / 128, NTOK / 128, 3);
    const dim3 g1(C_ / 128, NTOK / 128, 1);

    // QKV projections -> split q/k/v
    gemm_tc<<<g3, 256, GEMM_SMEM>>>(xhi, xlo, whi, wlo,
                                    nullptr, nullptr, qkvhi, qkvlo);

    // Causal flash attention -> split att
    flash_k<<<dim3(S_ / 128, B_ * H_), 256, FLASH_SMEM>>>(qkvhi, qkvlo,
                                                          atthi, attlo);

    // Output projection -> fp32 t0
    gemm_tc<<<g1, 256, GEMM_SMEM>>>(atthi, attlo, whi + 3 * CC, wlo + 3 * CC,
                                    t0, nullptr, nullptr, nullptr);

    // xln = LN1(t0 + x); split = LNff1(xln)   (fused double-LN)
    ln2x_k<<<NTOK, 128>>>(t0, x, ln1_w, ln1_b, xln,
                          ff_ln1_w, ff_ln1_b, t0hi, t0lo);

    // h = LN(x_ln) @ ff_w1 + b1
    gemm_tc<<<g1, 256, GEMM_SMEM>>>(t0hi, t0lo, whi + 4 * CC, wlo + 4 * CC,
                                    t1, ff_b1, nullptr, nullptr);

    // h = LN(h) @ ff_w2 + b2
    ln_k<<<NTOK, 128>>>(t1, nullptr, ff_ln2_w, ff_ln2_b, nullptr, t0hi, t0lo);
    gemm_tc<<<g1, 256, GEMM_SMEM>>>(t0hi, t0lo, whi + 5 * CC, wlo + 5 * CC,
                                    t1, ff_b2, nullptr, nullptr);

    // out = LN(h + x_ln)
    ln_k<<<NTOK, 128>>>(t1, xln, ln2_w, ln2_b, out, nullptr, nullptr);
}

// round 15
// speedup vs baseline: 1.1376x; 1.1376x over previous
#include <cuda_runtime.h>
#include <cuda_bf16.h>
#include <math.h>
#include <stdint.h>

#define B_ 4
#define S_ 2048
#define C_ 512
#define H_ 8
#define D_ 64
#define NTOK (B_ * S_)
#define ATT_SCALE 0.125f
#define LN_EPS 1e-5f
#define NC ((size_t)NTOK * C_)
#define CC ((size_t)C_ * C_)

// ---------------------------------------------------------------------------
// Scratch buffers
// ---------------------------------------------------------------------------
__device__ float g_t0 [NC];
__device__ float g_xln[NC];
__device__ float g_t1 [NC];

__device__ uint16_t g_xhi [NC],     g_xlo [NC];
__device__ uint16_t g_whi [6 * CC], g_wlo [6 * CC];
__device__ uint16_t g_qkvhi[3 * NC], g_qkvlo[3 * NC];
__device__ uint16_t g_atthi[NC],    g_attlo[NC];
__device__ uint16_t g_t0hi[NC],     g_t0lo[NC];

// ---------------------------------------------------------------------------
// Helpers
// ---------------------------------------------------------------------------
__device__ __forceinline__ uint32_t smem_u32(const void* p) {
    uint32_t a;
    asm("{ .reg .u64 t; cvta.to.shared.u64 t, %1; cvt.u32.u64 %0, t; }"
        : "=r"(a) : "l"(p));
    return a;
}
__device__ __forceinline__ void ldsm4(uint32_t* r, uint32_t addr) {
    asm volatile("ldmatrix.sync.aligned.m8n8.x4.shared.b16 {%0,%1,%2,%3}, [%4];"
                 : "=r"(r[0]), "=r"(r[1]), "=r"(r[2]), "=r"(r[3]) : "r"(addr));
}
__device__ __forceinline__ void ldsm4t(uint32_t* r, uint32_t addr) {
    asm volatile("ldmatrix.sync.aligned.m8n8.x4.trans.shared.b16 {%0,%1,%2,%3}, [%4];"
                 : "=r"(r[0]), "=r"(r[1]), "=r"(r[2]), "=r"(r[3]) : "r"(addr));
}
__device__ __forceinline__ void mma16816(float* c, const uint32_t* a, const uint32_t* b) {
    asm volatile(
        "mma.sync.aligned.m16n8k16.row.col.f32.bf16.bf16.f32 "
        "{%0,%1,%2,%3},{%4,%5,%6,%7},{%8,%9},{%0,%1,%2,%3};"
        : "+f"(c[0]), "+f"(c[1]), "+f"(c[2]), "+f"(c[3])
        : "r"(a[0]), "r"(a[1]), "r"(a[2]), "r"(a[3]), "r"(b[0]), "r"(b[1]));
}
__device__ __forceinline__ void cpa16(uint32_t dst, const void* src) {
    asm volatile("cp.async.cg.shared.global [%0], [%1], 16;" :: "r"(dst), "l"(src));
}
#define CPA_COMMIT() asm volatile("cp.async.commit_group;")
#define CPA_WAIT0()  asm volatile("cp.async.wait_group 0;")
#define CPA_WAIT1()  asm volatile("cp.async.wait_group 1;")

__device__ __forceinline__ uint16_t f2bf(float x) {
    __nv_bfloat16 b = __float2bfloat16(x);
    return *(uint16_t*)&b;
}
__device__ __forceinline__ float bf2f(uint16_t u) {
    __nv_bfloat16 b = *(__nv_bfloat16*)&u;
    return __bfloat162float(b);
}
__device__ __forceinline__ void split2(float x0, float x1, uint32_t& hi, uint32_t& lo) {
    uint16_t h0 = f2bf(x0), h1 = f2bf(x1);
    uint16_t l0 = f2bf(x0 - bf2f(h0)), l1 = f2bf(x1 - bf2f(h1));
    hi = (uint32_t)h0 | ((uint32_t)h1 << 16);
    lo = (uint32_t)l0 | ((uint32_t)l1 << 16);
}

// ---------------------------------------------------------------------------
// Split kernels
// ---------------------------------------------------------------------------
__global__ __launch_bounds__(256) void split1_k(
    const float* __restrict__ in, uint16_t* __restrict__ hi,
    uint16_t* __restrict__ lo)
{
    const size_t i = ((size_t)blockIdx.x * 256 + threadIdx.x) * 8;
    float4 a = *(const float4*)(in + i);
    float4 b = *(const float4*)(in + i + 4);
    uint32_t h0, l0, h1, l1, h2, l2, h3, l3;
    split2(a.x, a.y, h0, l0); split2(a.z, a.w, h1, l1);
    split2(b.x, b.y, h2, l2); split2(b.z, b.w, h3, l3);
    *(uint4*)(hi + i) = make_uint4(h0, h1, h2, h3);
    *(uint4*)(lo + i) = make_uint4(l0, l1, l2, l3);
}

__global__ __launch_bounds__(256) void splitw_k(
    const float* __restrict__ w0, const float* __restrict__ w1,
    const float* __restrict__ w2, const float* __restrict__ w3,
    const float* __restrict__ w4, const float* __restrict__ w5,
    uint16_t* __restrict__ hi, uint16_t* __restrict__ lo)
{
    const int z = blockIdx.z;
    const float* w = (z == 0) ? w0 : (z == 1) ? w1 : (z == 2) ? w2 :
                     (z == 3) ? w3 : (z == 4) ? w4 : w5;
    const size_t j = ((size_t)blockIdx.x * 256 + threadIdx.x) * 8;
    const size_t o = (size_t)z * CC + j;
    float4 a = *(const float4*)(w + j);
    float4 b = *(const float4*)(w + j + 4);
    uint32_t h0, l0, h1, l1, h2, l2, h3, l3;
    split2(a.x, a.y, h0, l0); split2(a.z, a.w, h1, l1);
    split2(b.x, b.y, h2, l2); split2(b.z, b.w, h3, l3);
    *(uint4*)(hi + o) = make_uint4(h0, h1, h2, h3);
    *(uint4*)(lo + o) = make_uint4(l0, l1, l2, l3);
}

// ---------------------------------------------------------------------------
// bf16x3 GEMM: 128x128 tile, BK=32, 256 threads, 3-stage cp.async ring,
// one __syncthreads per chunk (R12 proven config).
// ---------------------------------------------------------------------------
#define GSA 40
#define GSB 136
#define APL 10240
#define BPL 8704
#define STG 37888
#define GEMM_SMEM (3 * STG)     // 113664

__global__ __launch_bounds__(256) void gemm_tc(
    const uint16_t* __restrict__ Ahi, const uint16_t* __restrict__ Alo,
    const uint16_t* __restrict__ Whi, const uint16_t* __restrict__ Wlo,
    float* __restrict__ Cf, const float* __restrict__ bias,
    uint16_t* __restrict__ Chi, uint16_t* __restrict__ Clo)
{
    extern __shared__ char sm[];
    const uint32_t smb = smem_u32(sm);
    const int tid = threadIdx.x;
    const int wid = tid >> 5, lane = tid & 31;
    const int g = lane >> 2, tig = lane & 3;
    const int wm = wid >> 2, wn = wid & 3;
    const int n0 = blockIdx.x * 128, m0 = blockIdx.y * 128;
    const uint16_t* Wh = Whi + (size_t)blockIdx.z * CC;
    const uint16_t* Wl = Wlo + (size_t)blockIdx.z * CC;
    const size_t zO = (size_t)blockIdx.z * NC;

    float c[4][4][4];
#pragma unroll
    for (int i = 0; i < 4; i++)
#pragma unroll
        for (int j = 0; j < 4; j++)
#pragma unroll
            for (int e = 0; e < 4; e++) c[i][j][e] = 0.f;

    auto preload = [&](int chunk, int buf) {
        const uint32_t sb = smb + (uint32_t)buf * STG;
        const int k0 = chunk * 32;
#pragma unroll
        for (int rep = 0; rep < 2; rep++) {
            const int cc = tid + rep * 256;
            {
                const int row = cc >> 2, kc = cc & 3;
                const uint32_t d = sb + row * 80 + kc * 16;
                const size_t so = (size_t)(m0 + row) * C_ + k0 + kc * 8;
                cpa16(d, Ahi + so);
                cpa16(d + APL, Alo + so);
            }
            {
                const int row = cc >> 4, nc = cc & 15;
                const uint32_t d = sb + 2 * APL + row * 272 + nc * 16;
                const size_t so = (size_t)(k0 + row) * C_ + n0 + nc * 8;
                cpa16(d, Wh + so);
                cpa16(d + BPL, Wl + so);
            }
        }
    };

    auto compute = [&](int buf) {
        const uint32_t sb = smb + (uint32_t)buf * STG;
#pragma unroll
        for (int kk = 0; kk < 32; kk += 16) {
            uint32_t ah[4][4], al[4][4];
#pragma unroll
            for (int mf = 0; mf < 4; mf++) {
                const uint32_t ae =
                    (uint32_t)((wm * 64 + mf * 16 + (lane & 15)) * GSA +
                               kk + ((lane >> 4) << 3)) * 2;
                ldsm4(ah[mf], sb + ae);
                ldsm4(al[mf], sb + APL + ae);
            }
            uint32_t bh[4][2], bl[4][2];
#pragma unroll
            for (int nfp = 0; nfp < 2; nfp++) {
                const uint32_t be =
                    (uint32_t)((kk + (lane & 7) + (((lane >> 3) & 1) << 3)) * GSB +
                               wn * 32 + nfp * 16 + ((lane >> 4) << 3)) * 2;
                uint32_t r[4];
                ldsm4t(r, sb + 2 * APL + be);
                bh[nfp * 2][0] = r[0]; bh[nfp * 2][1] = r[1];
                bh[nfp * 2 + 1][0] = r[2]; bh[nfp * 2 + 1][1] = r[3];
                ldsm4t(r, sb + 2 * APL + BPL + be);
                bl[nfp * 2][0] = r[0]; bl[nfp * 2][1] = r[1];
                bl[nfp * 2 + 1][0] = r[2]; bl[nfp * 2 + 1][1] = r[3];
            }
#pragma unroll
            for (int mf = 0; mf < 4; mf++)
#pragma unroll
                for (int nf = 0; nf < 4; nf++) {
                    mma16816(c[mf][nf], ah[mf], bh[nf]);
                    mma16816(c[mf][nf], ah[mf], bl[nf]);
                    mma16816(c[mf][nf], al[mf], bh[nf]);
                }
        }
    };

    preload(0, 0);
    CPA_COMMIT();
    preload(1, 1);
    CPA_COMMIT();
    for (int ch = 0; ch < 16; ch++) {
        if (ch < 15) CPA_WAIT1(); else CPA_WAIT0();
        __syncthreads();
        if (ch + 2 < 16) {
            preload(ch + 2, (ch + 2) % 3);
            CPA_COMMIT();
        }
        compute(ch % 3);
    }

#pragma unroll
    for (int mf = 0; mf < 4; mf++) {
        const int row0 = m0 + wm * 64 + mf * 16 + g;
        const int row1 = row0 + 8;
#pragma unroll
        for (int nf = 0; nf < 4; nf++) {
            const int col = n0 + wn * 32 + nf * 8 + tig * 2;
            if (Cf) {
                float bx = 0.f, by = 0.f;
                if (bias) { bx = bias[col]; by = bias[col + 1]; }
                *(float2*)(Cf + (size_t)row0 * C_ + col) =
                    make_float2(c[mf][nf][0] + bx, c[mf][nf][1] + by);
                *(float2*)(Cf + (size_t)row1 * C_ + col) =
                    make_float2(c[mf][nf][2] + bx, c[mf][nf][3] + by);
            } else {
                uint32_t hi, lo;
                split2(c[mf][nf][0], c[mf][nf][1], hi, lo);
                *(uint32_t*)(Chi + zO + (size_t)row0 * C_ + col) = hi;
                *(uint32_t*)(Clo + zO + (size_t)row0 * C_ + col) = lo;
                split2(c[mf][nf][2], c[mf][nf][3], hi, lo);
                *(uint32_t*)(Chi + zO + (size_t)row1 * C_ + col) = hi;
                *(uint32_t*)(Clo + zO + (size_t)row1 * C_ + col) = lo;
            }
        }
    }
}

// ---------------------------------------------------------------------------
// LayerNorm
// ---------------------------------------------------------------------------
__device__ __forceinline__ void ln_row_stats(float4 v, int t, float& mean,
                                             float& inv, float* rs, float* rs2)
{
    float s  = v.x + v.y + v.z + v.w;
    float s2 = v.x * v.x + v.y * v.y + v.z * v.z + v.w * v.w;
#pragma unroll
    for (int o = 16; o; o >>= 1) {
        s  += __shfl_xor_sync(0xffffffffu, s,  o);
        s2 += __shfl_xor_sync(0xffffffffu, s2, o);
    }
    const int wid = t >> 5;
    if ((t & 31) == 0) { rs[wid] = s; rs2[wid] = s2; }
    __syncthreads();
    float S  = rs[0]  + rs[1]  + rs[2]  + rs[3];
    float S2 = rs2[0] + rs2[1] + rs2[2] + rs2[3];
    mean = S * (1.f / C_);
    const float var = S2 * (1.f / C_) - mean * mean;
    inv = rsqrtf(var + LN_EPS);
}

__global__ __launch_bounds__(128) void ln_k(
    const float* __restrict__ in, const float* __restrict__ res,
    const float* __restrict__ w, const float* __restrict__ b,
    float* __restrict__ out, uint16_t* __restrict__ ohi,
    uint16_t* __restrict__ olo)
{
    const int row = blockIdx.x;
    const int t = threadIdx.x;
    __shared__ float rs[4], rs2[4];

    float4 v = *(const float4*)(in + (size_t)row * C_ + t * 4);
    if (res) {
        float4 r = *(const float4*)(res + (size_t)row * C_ + t * 4);
        v.x += r.x; v.y += r.y; v.z += r.z; v.w += r.w;
    }
    float mean, inv;
    ln_row_stats(v, t, mean, inv, rs, rs2);

    float4 wv = *(const float4*)(w + t * 4);
    float4 bv = *(const float4*)(b + t * 4);
    float4 o;
    o.x = (v.x - mean) * inv * wv.x + bv.x;
    o.y = (v.y - mean) * inv * wv.y + bv.y;
    o.z = (v.z - mean) * inv * wv.z + bv.z;
    o.w = (v.w - mean) * inv * wv.w + bv.w;
    if (out)
        *(float4*)(out + (size_t)row * C_ + t * 4) = o;
    if (ohi) {
        uint32_t h0, l0, h1, l1;
        split2(o.x, o.y, h0, l0);
        split2(o.z, o.w, h1, l1);
        *(uint2*)(ohi + (size_t)row * C_ + t * 4) = make_uint2(h0, h1);
        *(uint2*)(olo + (size_t)row * C_ + t * 4) = make_uint2(l0, l1);
    }
}

// Fused double-LN: xln = LN1(in+res); split = LN2(xln).
__global__ __launch_bounds__(128) void ln2x_k(
    const float* __restrict__ in, const float* __restrict__ res,
    const float* __restrict__ w1, const float* __restrict__ b1,
    float* __restrict__ xln_out,
    const float* __restrict__ w2, const float* __restrict__ b2,
    uint16_t* __restrict__ ohi, uint16_t* __restrict__ olo)
{
    const int row = blockIdx.x;
    const int t = threadIdx.x;
    __shared__ float rs[4], rs2[4];

    float4 v = *(const float4*)(in + (size_t)row * C_ + t * 4);
    float4 r = *(const float4*)(res + (size_t)row * C_ + t * 4);
    v.x += r.x; v.y += r.y; v.z += r.z; v.w += r.w;

    float mean, inv;
    ln_row_stats(v, t, mean, inv, rs, rs2);

    float4 w1v = *(const float4*)(w1 + t * 4);
    float4 b1v = *(const float4*)(b1 + t * 4);
    float4 x1;
    x1.x = (v.x - mean) * inv * w1v.x + b1v.x;
    x1.y = (v.y - mean) * inv * w1v.y + b1v.y;
    x1.z = (v.z - mean) * inv * w1v.z + b1v.z;
    x1.w = (v.w - mean) * inv * w1v.w + b1v.w;
    *(float4*)(xln_out + (size_t)row * C_ + t * 4) = x1;

    __syncthreads();
    float mean2, inv2;
    ln_row_stats(x1, t, mean2, inv2, rs, rs2);

    float4 w2v = *(const float4*)(w2 + t * 4);
    float4 b2v = *(const float4*)(b2 + t * 4);
    float4 o;
    o.x = (x1.x - mean2) * inv2 * w2v.x + b2v.x;
    o.y = (x1.y - mean2) * inv2 * w2v.y + b2v.y;
    o.z = (x1.z - mean2) * inv2 * w2v.z + b2v.z;
    o.w = (x1.w - mean2) * inv2 * w2v.w + b2v.w;
    uint32_t h0, l0, h1, l1;
    split2(o.x, o.y, h0, l0);
    split2(o.z, o.w, h1, l1);
    *(uint2*)(ohi + (size_t)row * C_ + t * 4) = make_uint2(h0, h1);
    *(uint2*)(olo + (size_t)row * C_ + t * 4) = make_uint2(l0, l1);
}

// ---------------------------------------------------------------------------
// FA2-style flash attention. Grid = (bh, qt) so heavy q-tiles (high qt)
// are scheduled first ACROSS ALL heads (LPT order); body unchanged from R12.
// ---------------------------------------------------------------------------
#define FS 72
#define PLANE 9216
#define BUFSZ (4 * PLANE)
#define FLASH_SMEM (2 * BUFSZ)

__global__ __launch_bounds__(256, 1) void flash_k(
    const uint16_t* __restrict__ QKVhi, const uint16_t* __restrict__ QKVlo,
    uint16_t* __restrict__ Ohi, uint16_t* __restrict__ Olo)
{
    extern __shared__ char sm[];
    const uint32_t smb = smem_u32(sm);

    const int tid = threadIdx.x;
    const int wid = tid >> 5, lane = tid & 31;
    const int g = lane >> 2, tig = lane & 3;

    const int qt = (gridDim.y - 1) - blockIdx.y;   // heavy tiles first (global)
    const int bh = blockIdx.x;
    const int b  = bh >> 3, h = bh & 7;
    const size_t base = (size_t)b * S_ * C_ + (size_t)h * D_;
    const int q0 = qt * 128;
    const int wr0 = wid * 16;

    const uint16_t* Qhi = QKVhi + base;
    const uint16_t* Qlo = QKVlo + base;
    const uint16_t* Khi = QKVhi + NC + base;
    const uint16_t* Klo = QKVlo + NC + base;
    const uint16_t* Vhi = QKVhi + 2 * NC + base;
    const uint16_t* Vlo = QKVlo + 2 * NC + base;

#pragma unroll
    for (int p = 0; p < 8; p++) {
        const int id = p * 256 + tid;
        const int half = id >> 10;
        const int pl = (id >> 9) & 1;
        const int rl = (id & 511) >> 3;
        const int ch = id & 7;
        const uint32_t dst = smb + (half * 2 + pl) * PLANE +
                             (uint32_t)(rl * FS + ch * 8) * 2;
        const uint16_t* src = (pl ? Qlo : Qhi) +
                              (size_t)(q0 + half * 64 + rl) * C_ + ch * 8;
        cpa16(dst, src);
    }
    CPA_COMMIT();
    CPA_WAIT0();
    __syncthreads();

    uint32_t qh[4][4], ql[4][4];
    {
        const uint32_t areaH = smb + ((wid >= 4) ? 2 * PLANE : 0);
        const int lw = (wid & 3) * 16;
#pragma unroll
        for (int kf = 0; kf < 4; kf++) {
            const uint32_t ae =
                (uint32_t)((lw + (lane & 15)) * FS + kf * 16 +
                           ((lane >> 4) << 3)) * 2;
            ldsm4(qh[kf], areaH + ae);
            ldsm4(ql[kf], areaH + PLANE + ae);
        }
    }
    __syncthreads();

    float acc[8][4];
#pragma unroll
    for (int i = 0; i < 8; i++)
#pragma unroll
        for (int e = 0; e < 4; e++) acc[i][e] = 0.f;
    float m0 = -1e30f, m1 = -1e30f, l0 = 0.f, l1 = 0.f;

    const int r0 = q0 + wr0 + g;
    const int r1 = r0 + 8;
    const int nkt = 2 * qt + 2;

    auto preload = [&](int kt, int buf) {
        const int k0 = kt * 64;
        const uint32_t bb = smb + buf * BUFSZ;
#pragma unroll
        for (int p = 0; p < 8; p++) {
            const int id = p * 256 + tid;
            const int pl = id >> 9;
            const int rl = (id & 511) >> 3;
            const int ch = id & 7;
            const uint32_t dst = bb + pl * PLANE +
                                 (uint32_t)(rl * FS + ch * 8) * 2;
            const uint16_t* src =
                ((pl == 0) ? Khi : (pl == 1) ? Klo : (pl == 2) ? Vhi : Vlo) +
                (size_t)(k0 + rl) * C_ + ch * 8;
            cpa16(dst, src);
        }
    };

    preload(0, 0);
    CPA_COMMIT();

    for (int kt = 0; kt < nkt; kt++) {
        const int k0g = kt * 64;
        CPA_WAIT0();
        __syncthreads();
        if (kt + 1 < nkt) {
            preload(kt + 1, (kt + 1) & 1);
            CPA_COMMIT();
        }

        if (k0g <= q0 + wr0 + 15) {
            const uint32_t kb = smb + (kt & 1) * BUFSZ;

            float s[8][4];
#pragma unroll
            for (int i = 0; i < 8; i++)
#pragma unroll
                for (int e = 0; e < 4; e++) s[i][e] = 0.f;

#pragma unroll
            for (int kf = 0; kf < 4; kf++) {
#pragma unroll
                for (int nfq = 0; nfq < 4; nfq++) {
                    const uint32_t be =
                        (uint32_t)((nfq * 16 + (lane & 7) + ((lane >> 4) << 3)) * FS +
                                   kf * 16 + (((lane >> 3) & 1) << 3)) * 2;
                    uint32_t rh[4], rl_[4];
                    ldsm4(rh, kb + be);
                    ldsm4(rl_, kb + PLANE + be);
                    mma16816(s[2 * nfq], qh[kf], rh);
                    mma16816(s[2 * nfq], qh[kf], rl_);
                    mma16816(s[2 * nfq], ql[kf], rh);
                    mma16816(s[2 * nfq + 1], qh[kf], rh + 2);
                    mma16816(s[2 * nfq + 1], qh[kf], rl_ + 2);
                    mma16816(s[2 * nfq + 1], ql[kf], rh + 2);
                }
            }

            const bool needmask = (k0g + 63 > q0 + wr0);
#pragma unroll
            for (int nf = 0; nf < 8; nf++) {
#pragma unroll
                for (int e = 0; e < 4; e++) s[nf][e] *= ATT_SCALE;
                if (needmask) {
                    const int cc = k0g + nf * 8 + tig * 2;
                    if (cc     > r0) s[nf][0] = -1e30f;
                    if (cc + 1 > r0) s[nf][1] = -1e30f;
                    if (cc     > r1) s[nf][2] = -1e30f;
                    if (cc + 1 > r1) s[nf][3] = -1e30f;
                }
            }

            float ml0 = -1e30f, ml1 = -1e30f;
#pragma unroll
            for (int nf = 0; nf < 8; nf++) {
                ml0 = fmaxf(ml0, fmaxf(s[nf][0], s[nf][1]));
                ml1 = fmaxf(ml1, fmaxf(s[nf][2], s[nf][3]));
            }
            ml0 = fmaxf(ml0, __shfl_xor_sync(0xffffffffu, ml0, 1));
            ml0 = fmaxf(ml0, __shfl_xor_sync(0xffffffffu, ml0, 2));
            ml1 = fmaxf(ml1, __shfl_xor_sync(0xffffffffu, ml1, 1));
            ml1 = fmaxf(ml1, __shfl_xor_sync(0xffffffffu, ml1, 2));

            const float mn0 = fmaxf(m0, ml0);
            const float mn1 = fmaxf(m1, ml1);
            const float cr0 = __expf(m0 - mn0);
            const float cr1 = __expf(m1 - mn1);
            m0 = mn0; m1 = mn1;

            float rs0 = 0.f, rs1 = 0.f;
#pragma unroll
            for (int nf = 0; nf < 8; nf++) {
                s[nf][0] = __expf(s[nf][0] - mn0);
                s[nf][1] = __expf(s[nf][1] - mn0);
                s[nf][2] = __expf(s[nf][2] - mn1);
                s[nf][3] = __expf(s[nf][3] - mn1);
                rs0 += s[nf][0] + s[nf][1];
                rs1 += s[nf][2] + s[nf][3];
                acc[nf][0] *= cr0; acc[nf][1] *= cr0;
                acc[nf][2] *= cr1; acc[nf][3] *= cr1;
            }
            rs0 += __shfl_xor_sync(0xffffffffu, rs0, 1);
            rs0 += __shfl_xor_sync(0xffffffffu, rs0, 2);
            rs1 += __shfl_xor_sync(0xffffffffu, rs1, 1);
            rs1 += __shfl_xor_sync(0xffffffffu, rs1, 2);
            l0 = l0 * cr0 + rs0;
            l1 = l1 * cr1 + rs1;

#pragma unroll
            for (int kf = 0; kf < 4; kf++) {
                uint32_t aph[4], apl[4];
                split2(s[2 * kf][0],     s[2 * kf][1],     aph[0], apl[0]);
                split2(s[2 * kf][2],     s[2 * kf][3],     aph[1], apl[1]);
                split2(s[2 * kf + 1][0], s[2 * kf + 1][1], aph[2], apl[2]);
                split2(s[2 * kf + 1][2], s[2 * kf + 1][3], aph[3], apl[3]);
#pragma unroll
                for (int nfq = 0; nfq < 4; nfq++) {
                    const uint32_t be =
                        (uint32_t)((kf * 16 + (lane & 7) + (((lane >> 3) & 1) << 3)) * FS +
                                   nfq * 16 + ((lane >> 4) << 3)) * 2;
                    uint32_t vh[4], vl[4];
                    ldsm4t(vh, kb + 2 * PLANE + be);
                    ldsm4t(vl, kb + 3 * PLANE + be);
                    mma16816(acc[2 * nfq], aph, vh);
                    mma16816(acc[2 * nfq], aph, vl);
                    mma16816(acc[2 * nfq], apl, vh);
                    mma16816(acc[2 * nfq + 1], aph, vh + 2);
                    mma16816(acc[2 * nfq + 1], aph, vl + 2);
                    mma16816(acc[2 * nfq + 1], apl, vh + 2);
                }
            }
        }
    }

    const float il0 = 1.f / l0;
    const float il1 = 1.f / l1;
#pragma unroll
    for (int nf = 0; nf < 8; nf++) {
        const int col = nf * 8 + tig * 2;
        uint32_t hi, lo;
        split2(acc[nf][0] * il0, acc[nf][1] * il0, hi, lo);
        *(uint32_t*)(Ohi + base + (size_t)r0 * C_ + col) = hi;
        *(uint32_t*)(Olo + base + (size_t)r0 * C_ + col) = lo;
        split2(acc[nf][2] * il1, acc[nf][3] * il1, hi, lo);
        *(uint32_t*)(Ohi + base + (size_t)r1 * C_ + col) = hi;
        *(uint32_t*)(Olo + base + (size_t)r1 * C_ + col) = lo;
    }
}

// ---------------------------------------------------------------------------
// Launcher
// ---------------------------------------------------------------------------
extern "C" void kernel_launch(void* const* d_in, const int* in_sizes, int n_in,
                              void* d_out, int out_size)
{
    (void)in_sizes; (void)n_in; (void)out_size;

    const float* x        = (const float*)d_in[0];
    const float* Wq       = (const float*)d_in[1];
    const float* Wk       = (const float*)d_in[2];
    const float* Wv       = (const float*)d_in[3];
    const float* Wo       = (const float*)d_in[4];
    const float* ln1_w    = (const float*)d_in[5];
    const float* ln1_b    = (const float*)d_in[6];
    const float* ff_ln1_w = (const float*)d_in[7];
    const float* ff_ln1_b = (const float*)d_in[8];
    const float* ff_w1    = (const float*)d_in[9];
    const float* ff_b1    = (const float*)d_in[10];
    const float* ff_ln2_w = (const float*)d_in[11];
    const float* ff_ln2_b = (const float*)d_in[12];
    const float* ff_w2    = (const float*)d_in[13];
    const float* ff_b2    = (const float*)d_in[14];
    const float* ln2_w    = (const float*)d_in[15];
    const float* ln2_b    = (const float*)d_in[16];
    float* out = (float*)d_out;

    float *t0, *xln, *t1;
    uint16_t *xhi, *xlo, *whi, *wlo, *qkvhi, *qkvlo, *atthi, *attlo, *t0hi, *t0lo;
    cudaGetSymbolAddress((void**)&t0,    g_t0);
    cudaGetSymbolAddress((void**)&xln,   g_xln);
    cudaGetSymbolAddress((void**)&t1,    g_t1);
    cudaGetSymbolAddress((void**)&xhi,   g_xhi);
    cudaGetSymbolAddress((void**)&xlo,   g_xlo);
    cudaGetSymbolAddress((void**)&whi,   g_whi);
    cudaGetSymbolAddress((void**)&wlo,   g_wlo);
    cudaGetSymbolAddress((void**)&qkvhi, g_qkvhi);
    cudaGetSymbolAddress((void**)&qkvlo, g_qkvlo);
    cudaGetSymbolAddress((void**)&atthi, g_atthi);
    cudaGetSymbolAddress((void**)&attlo, g_attlo);
    cudaGetSymbolAddress((void**)&t0hi,  g_t0hi);
    cudaGetSymbolAddress((void**)&t0lo,  g_t0lo);

    cudaFuncSetAttribute(flash_k, cudaFuncAttributeMaxDynamicSharedMemorySize,
                         FLASH_SMEM);
    cudaFuncSetAttribute(gemm_tc, cudaFuncAttributeMaxDynamicSharedMemorySize,
                         GEMM_SMEM);

    // Split inputs
    split1_k<<<(int)(NC / 2048), 256>>>(x, xhi, xlo);
    splitw_k<<<dim3((int)(CC / 2048), 1, 6), 256>>>(Wq, Wk, Wv, Wo, ff_w1, ff_w2,
                                                    whi, wlo);

    const dim3 g3(C_ / 128, NTOK / 128, 3);
    const dim3 g1(C_ / 128, NTOK / 128, 1);

    // QKV projections -> split q/k/v
    gemm_tc<<<g3, 256, GEMM_SMEM>>>(xhi, xlo, whi, wlo,
                                    nullptr, nullptr, qkvhi, qkvlo);

    // Causal flash attention -> split att  (grid: bh-major, heavy qt first)
    flash_k<<<dim3(B_ * H_, S_ / 128), 256, FLASH_SMEM>>>(qkvhi, qkvlo,
                                                          atthi, attlo);

    // Output projection -> fp32 t0
    gemm_tc<<<g1, 256, GEMM_SMEM>>>(atthi, attlo, whi + 3 * CC, wlo + 3 * CC,
                                    t0, nullptr, nullptr, nullptr);

    // xln = LN1(t0 + x); split = LNff1(xln)   (fused double-LN)
    ln2x_k<<<NTOK, 128>>>(t0, x, ln1_w, ln1_b, xln,
                          ff_ln1_w, ff_ln1_b, t0hi, t0lo);

    // h = LN(x_ln) @ ff_w1 + b1
    gemm_tc<<<g1, 256, GEMM_SMEM>>>(t0hi, t0lo, whi + 4 * CC, wlo + 4 * CC,
                                    t1, ff_b1, nullptr, nullptr);

    // h = LN(h) @ ff_w2 + b2
    ln_k<<<NTOK, 128>>>(t1, nullptr, ff_ln2_w, ff_ln2_b, nullptr, t0hi, t0lo);
    gemm_tc<<<g1, 256, GEMM_SMEM>>>(t0hi, t0lo, whi + 5 * CC, wlo + 5 * CC,
                                    t1, ff_b2, nullptr, nullptr);

    // out = LN(h + x_ln)
    ln_k<<<NTOK, 128>>>(t1, xln, ln2_w, ln2_b, out, nullptr, nullptr);
}

// round 16
// speedup vs baseline: 1.1654x; 1.0244x over previous
#include <cuda_runtime.h>
#include <cuda_bf16.h>
#include <math.h>
#include <stdint.h>

#define B_ 4
#define S_ 2048
#define C_ 512
#define H_ 8
#define D_ 64
#define NTOK (B_ * S_)
#define ATT_SCALE 0.125f
#define LN_EPS 1e-5f
#define NC ((size_t)NTOK * C_)
#define CC ((size_t)C_ * C_)

// ---------------------------------------------------------------------------
// Scratch buffers
// ---------------------------------------------------------------------------
__device__ float g_t0 [NC];
__device__ float g_xln[NC];
__device__ float g_t1 [NC];

__device__ uint16_t g_xhi [NC],     g_xlo [NC];
__device__ uint16_t g_whi [6 * CC], g_wlo [6 * CC];
__device__ uint16_t g_qkvhi[3 * NC], g_qkvlo[3 * NC];
__device__ uint16_t g_atthi[NC],    g_attlo[NC];
__device__ uint16_t g_t0hi[NC],     g_t0lo[NC];

// ---------------------------------------------------------------------------
// Helpers
// ---------------------------------------------------------------------------
__device__ __forceinline__ uint32_t smem_u32(const void* p) {
    uint32_t a;
    asm("{ .reg .u64 t; cvta.to.shared.u64 t, %1; cvt.u32.u64 %0, t; }"
        : "=r"(a) : "l"(p));
    return a;
}
__device__ __forceinline__ void ldsm4(uint32_t* r, uint32_t addr) {
    asm volatile("ldmatrix.sync.aligned.m8n8.x4.shared.b16 {%0,%1,%2,%3}, [%4];"
                 : "=r"(r[0]), "=r"(r[1]), "=r"(r[2]), "=r"(r[3]) : "r"(addr));
}
__device__ __forceinline__ void ldsm4t(uint32_t* r, uint32_t addr) {
    asm volatile("ldmatrix.sync.aligned.m8n8.x4.trans.shared.b16 {%0,%1,%2,%3}, [%4];"
                 : "=r"(r[0]), "=r"(r[1]), "=r"(r[2]), "=r"(r[3]) : "r"(addr));
}
__device__ __forceinline__ void mma16816(float* c, const uint32_t* a, const uint32_t* b) {
    asm volatile(
        "mma.sync.aligned.m16n8k16.row.col.f32.bf16.bf16.f32 "
        "{%0,%1,%2,%3},{%4,%5,%6,%7},{%8,%9},{%0,%1,%2,%3};"
        : "+f"(c[0]), "+f"(c[1]), "+f"(c[2]), "+f"(c[3])
        : "r"(a[0]), "r"(a[1]), "r"(a[2]), "r"(a[3]), "r"(b[0]), "r"(b[1]));
}
__device__ __forceinline__ void cpa16(uint32_t dst, const void* src) {
    asm volatile("cp.async.cg.shared.global [%0], [%1], 16;" :: "r"(dst), "l"(src));
}
#define CPA_COMMIT() asm volatile("cp.async.commit_group;")
#define CPA_WAIT0()  asm volatile("cp.async.wait_group 0;")
#define CPA_WAIT1()  asm volatile("cp.async.wait_group 1;")

__device__ __forceinline__ uint16_t f2bf(float x) {
    __nv_bfloat16 b = __float2bfloat16(x);
    return *(uint16_t*)&b;
}
__device__ __forceinline__ float bf2f(uint16_t u) {
    __nv_bfloat16 b = *(__nv_bfloat16*)&u;
    return __bfloat162float(b);
}
__device__ __forceinline__ void split2(float x0, float x1, uint32_t& hi, uint32_t& lo) {
    uint16_t h0 = f2bf(x0), h1 = f2bf(x1);
    uint16_t l0 = f2bf(x0 - bf2f(h0)), l1 = f2bf(x1 - bf2f(h1));
    hi = (uint32_t)h0 | ((uint32_t)h1 << 16);
    lo = (uint32_t)l0 | ((uint32_t)l1 << 16);
}

// ---------------------------------------------------------------------------
// Split kernels
// ---------------------------------------------------------------------------
__global__ __launch_bounds__(256) void split1_k(
    const float* __restrict__ in, uint16_t* __restrict__ hi,
    uint16_t* __restrict__ lo)
{
    const size_t i = ((size_t)blockIdx.x * 256 + threadIdx.x) * 8;
    float4 a = *(const float4*)(in + i);
    float4 b = *(const float4*)(in + i + 4);
    uint32_t h0, l0, h1, l1, h2, l2, h3, l3;
    split2(a.x, a.y, h0, l0); split2(a.z, a.w, h1, l1);
    split2(b.x, b.y, h2, l2); split2(b.z, b.w, h3, l3);
    *(uint4*)(hi + i) = make_uint4(h0, h1, h2, h3);
    *(uint4*)(lo + i) = make_uint4(l0, l1, l2, l3);
}

__global__ __launch_bounds__(256) void splitw_k(
    const float* __restrict__ w0, const float* __restrict__ w1,
    const float* __restrict__ w2, const float* __restrict__ w3,
    const float* __restrict__ w4, const float* __restrict__ w5,
    uint16_t* __restrict__ hi, uint16_t* __restrict__ lo)
{
    const int z = blockIdx.z;
    const float* w = (z == 0) ? w0 : (z == 1) ? w1 : (z == 2) ? w2 :
                     (z == 3) ? w3 : (z == 4) ? w4 : w5;
    const size_t j = ((size_t)blockIdx.x * 256 + threadIdx.x) * 8;
    const size_t o = (size_t)z * CC + j;
    float4 a = *(const float4*)(w + j);
    float4 b = *(const float4*)(w + j + 4);
    uint32_t h0, l0, h1, l1, h2, l2, h3, l3;
    split2(a.x, a.y, h0, l0); split2(a.z, a.w, h1, l1);
    split2(b.x, b.y, h2, l2); split2(b.z, b.w, h3, l3);
    *(uint4*)(hi + o) = make_uint4(h0, h1, h2, h3);
    *(uint4*)(lo + o) = make_uint4(l0, l1, l2, l3);
}

// ---------------------------------------------------------------------------
// bf16x3 GEMM: 128x128 tile, BK=32, 256 threads, 3-stage cp.async ring,
// one __syncthreads per chunk (R12 config). oscale multiplies the split
// output for blockIdx.z==0 (used to fold ATT_SCALE into Q; 0.125 is exact).
// ---------------------------------------------------------------------------
#define GSA 40
#define GSB 136
#define APL 10240
#define BPL 8704
#define STG 37888
#define GEMM_SMEM (3 * STG)     // 113664

__global__ __launch_bounds__(256) void gemm_tc(
    const uint16_t* __restrict__ Ahi, const uint16_t* __restrict__ Alo,
    const uint16_t* __restrict__ Whi, const uint16_t* __restrict__ Wlo,
    float* __restrict__ Cf, const float* __restrict__ bias,
    uint16_t* __restrict__ Chi, uint16_t* __restrict__ Clo,
    float oscale)
{
    extern __shared__ char sm[];
    const uint32_t smb = smem_u32(sm);
    const int tid = threadIdx.x;
    const int wid = tid >> 5, lane = tid & 31;
    const int g = lane >> 2, tig = lane & 3;
    const int wm = wid >> 2, wn = wid & 3;
    const int n0 = blockIdx.x * 128, m0 = blockIdx.y * 128;
    const uint16_t* Wh = Whi + (size_t)blockIdx.z * CC;
    const uint16_t* Wl = Wlo + (size_t)blockIdx.z * CC;
    const size_t zO = (size_t)blockIdx.z * NC;
    const float sc = (blockIdx.z == 0) ? oscale : 1.f;

    float c[4][4][4];
#pragma unroll
    for (int i = 0; i < 4; i++)
#pragma unroll
        for (int j = 0; j < 4; j++)
#pragma unroll
            for (int e = 0; e < 4; e++) c[i][j][e] = 0.f;

    auto preload = [&](int chunk, int buf) {
        const uint32_t sb = smb + (uint32_t)buf * STG;
        const int k0 = chunk * 32;
#pragma unroll
        for (int rep = 0; rep < 2; rep++) {
            const int cc = tid + rep * 256;
            {
                const int row = cc >> 2, kc = cc & 3;
                const uint32_t d = sb + row * 80 + kc * 16;
                const size_t so = (size_t)(m0 + row) * C_ + k0 + kc * 8;
                cpa16(d, Ahi + so);
                cpa16(d + APL, Alo + so);
            }
            {
                const int row = cc >> 4, nc = cc & 15;
                const uint32_t d = sb + 2 * APL + row * 272 + nc * 16;
                const size_t so = (size_t)(k0 + row) * C_ + n0 + nc * 8;
                cpa16(d, Wh + so);
                cpa16(d + BPL, Wl + so);
            }
        }
    };

    auto compute = [&](int buf) {
        const uint32_t sb = smb + (uint32_t)buf * STG;
#pragma unroll
        for (int kk = 0; kk < 32; kk += 16) {
            uint32_t ah[4][4], al[4][4];
#pragma unroll
            for (int mf = 0; mf < 4; mf++) {
                const uint32_t ae =
                    (uint32_t)((wm * 64 + mf * 16 + (lane & 15)) * GSA +
                               kk + ((lane >> 4) << 3)) * 2;
                ldsm4(ah[mf], sb + ae);
                ldsm4(al[mf], sb + APL + ae);
            }
            uint32_t bh[4][2], bl[4][2];
#pragma unroll
            for (int nfp = 0; nfp < 2; nfp++) {
                const uint32_t be =
                    (uint32_t)((kk + (lane & 7) + (((lane >> 3) & 1) << 3)) * GSB +
                               wn * 32 + nfp * 16 + ((lane >> 4) << 3)) * 2;
                uint32_t r[4];
                ldsm4t(r, sb + 2 * APL + be);
                bh[nfp * 2][0] = r[0]; bh[nfp * 2][1] = r[1];
                bh[nfp * 2 + 1][0] = r[2]; bh[nfp * 2 + 1][1] = r[3];
                ldsm4t(r, sb + 2 * APL + BPL + be);
                bl[nfp * 2][0] = r[0]; bl[nfp * 2][1] = r[1];
                bl[nfp * 2 + 1][0] = r[2]; bl[nfp * 2 + 1][1] = r[3];
            }
#pragma unroll
            for (int mf = 0; mf < 4; mf++)
#pragma unroll
                for (int nf = 0; nf < 4; nf++) {
                    mma16816(c[mf][nf], ah[mf], bh[nf]);
                    mma16816(c[mf][nf], ah[mf], bl[nf]);
                    mma16816(c[mf][nf], al[mf], bh[nf]);
                }
        }
    };

    preload(0, 0);
    CPA_COMMIT();
    preload(1, 1);
    CPA_COMMIT();
    for (int ch = 0; ch < 16; ch++) {
        if (ch < 15) CPA_WAIT1(); else CPA_WAIT0();
        __syncthreads();
        if (ch + 2 < 16) {
            preload(ch + 2, (ch + 2) % 3);
            CPA_COMMIT();
        }
        compute(ch % 3);
    }

#pragma unroll
    for (int mf = 0; mf < 4; mf++) {
        const int row0 = m0 + wm * 64 + mf * 16 + g;
        const int row1 = row0 + 8;
#pragma unroll
        for (int nf = 0; nf < 4; nf++) {
            const int col = n0 + wn * 32 + nf * 8 + tig * 2;
            if (Cf) {
                float bx = 0.f, by = 0.f;
                if (bias) { bx = bias[col]; by = bias[col + 1]; }
                *(float2*)(Cf + (size_t)row0 * C_ + col) =
                    make_float2(c[mf][nf][0] + bx, c[mf][nf][1] + by);
                *(float2*)(Cf + (size_t)row1 * C_ + col) =
                    make_float2(c[mf][nf][2] + bx, c[mf][nf][3] + by);
            } else {
                uint32_t hi, lo;
                split2(c[mf][nf][0] * sc, c[mf][nf][1] * sc, hi, lo);
                *(uint32_t*)(Chi + zO + (size_t)row0 * C_ + col) = hi;
                *(uint32_t*)(Clo + zO + (size_t)row0 * C_ + col) = lo;
                split2(c[mf][nf][2] * sc, c[mf][nf][3] * sc, hi, lo);
                *(uint32_t*)(Chi + zO + (size_t)row1 * C_ + col) = hi;
                *(uint32_t*)(Clo + zO + (size_t)row1 * C_ + col) = lo;
            }
        }
    }
}

// ---------------------------------------------------------------------------
// LayerNorm
// ---------------------------------------------------------------------------
__device__ __forceinline__ void ln_row_stats(float4 v, int t, float& mean,
                                             float& inv, float* rs, float* rs2)
{
    float s  = v.x + v.y + v.z + v.w;
    float s2 = v.x * v.x + v.y * v.y + v.z * v.z + v.w * v.w;
#pragma unroll
    for (int o = 16; o; o >>= 1) {
        s  += __shfl_xor_sync(0xffffffffu, s,  o);
        s2 += __shfl_xor_sync(0xffffffffu, s2, o);
    }
    const int wid = t >> 5;
    if ((t & 31) == 0) { rs[wid] = s; rs2[wid] = s2; }
    __syncthreads();
    float S  = rs[0]  + rs[1]  + rs[2]  + rs[3];
    float S2 = rs2[0] + rs2[1] + rs2[2] + rs2[3];
    mean = S * (1.f / C_);
    const float var = S2 * (1.f / C_) - mean * mean;
    inv = rsqrtf(var + LN_EPS);
}

__global__ __launch_bounds__(128) void ln_k(
    const float* __restrict__ in, const float* __restrict__ res,
    const float* __restrict__ w, const float* __restrict__ b,
    float* __restrict__ out, uint16_t* __restrict__ ohi,
    uint16_t* __restrict__ olo)
{
    const int row = blockIdx.x;
    const int t = threadIdx.x;
    __shared__ float rs[4], rs2[4];

    float4 v = *(const float4*)(in + (size_t)row * C_ + t * 4);
    if (res) {
        float4 r = *(const float4*)(res + (size_t)row * C_ + t * 4);
        v.x += r.x; v.y += r.y; v.z += r.z; v.w += r.w;
    }
    float mean, inv;
    ln_row_stats(v, t, mean, inv, rs, rs2);

    float4 wv = *(const float4*)(w + t * 4);
    float4 bv = *(const float4*)(b + t * 4);
    float4 o;
    o.x = (v.x - mean) * inv * wv.x + bv.x;
    o.y = (v.y - mean) * inv * wv.y + bv.y;
    o.z = (v.z - mean) * inv * wv.z + bv.z;
    o.w = (v.w - mean) * inv * wv.w + bv.w;
    if (out)
        *(float4*)(out + (size_t)row * C_ + t * 4) = o;
    if (ohi) {
        uint32_t h0, l0, h1, l1;
        split2(o.x, o.y, h0, l0);
        split2(o.z, o.w, h1, l1);
        *(uint2*)(ohi + (size_t)row * C_ + t * 4) = make_uint2(h0, h1);
        *(uint2*)(olo + (size_t)row * C_ + t * 4) = make_uint2(l0, l1);
    }
}

// Fused double-LN: xln = LN1(in+res); split = LN2(xln).
__global__ __launch_bounds__(128) void ln2x_k(
    const float* __restrict__ in, const float* __restrict__ res,
    const float* __restrict__ w1, const float* __restrict__ b1,
    float* __restrict__ xln_out,
    const float* __restrict__ w2, const float* __restrict__ b2,
    uint16_t* __restrict__ ohi, uint16_t* __restrict__ olo)
{
    const int row = blockIdx.x;
    const int t = threadIdx.x;
    __shared__ float rs[4], rs2[4];

    float4 v = *(const float4*)(in + (size_t)row * C_ + t * 4);
    float4 r = *(const float4*)(res + (size_t)row * C_ + t * 4);
    v.x += r.x; v.y += r.y; v.z += r.z; v.w += r.w;

    float mean, inv;
    ln_row_stats(v, t, mean, inv, rs, rs2);

    float4 w1v = *(const float4*)(w1 + t * 4);
    float4 b1v = *(const float4*)(b1 + t * 4);
    float4 x1;
    x1.x = (v.x - mean) * inv * w1v.x + b1v.x;
    x1.y = (v.y - mean) * inv * w1v.y + b1v.y;
    x1.z = (v.z - mean) * inv * w1v.z + b1v.z;
    x1.w = (v.w - mean) * inv * w1v.w + b1v.w;
    *(float4*)(xln_out + (size_t)row * C_ + t * 4) = x1;

    __syncthreads();
    float mean2, inv2;
    ln_row_stats(x1, t, mean2, inv2, rs, rs2);

    float4 w2v = *(const float4*)(w2 + t * 4);
    float4 b2v = *(const float4*)(b2 + t * 4);
    float4 o;
    o.x = (x1.x - mean2) * inv2 * w2v.x + b2v.x;
    o.y = (x1.y - mean2) * inv2 * w2v.y + b2v.y;
    o.z = (x1.z - mean2) * inv2 * w2v.z + b2v.z;
    o.w = (x1.w - mean2) * inv2 * w2v.w + b2v.w;
    uint32_t h0, l0, h1, l1;
    split2(o.x, o.y, h0, l0);
    split2(o.z, o.w, h1, l1);
    *(uint2*)(ohi + (size_t)row * C_ + t * 4) = make_uint2(h0, h1);
    *(uint2*)(olo + (size_t)row * C_ + t * 4) = make_uint2(l0, l1);
}

// ---------------------------------------------------------------------------
// FA2-style flash attention. Grid = (bh, qt), heavy q-tiles first (LPT).
// Q pre-scaled by ATT_SCALE (folded into QKV gemm epilogue, exact).
// Row-sum l kept lane-partial; quad-reduced only in the epilogue.
// ---------------------------------------------------------------------------
#define FS 72
#define PLANE 9216
#define BUFSZ (4 * PLANE)
#define FLASH_SMEM (2 * BUFSZ)

__global__ __launch_bounds__(256, 1) void flash_k(
    const uint16_t* __restrict__ QKVhi, const uint16_t* __restrict__ QKVlo,
    uint16_t* __restrict__ Ohi, uint16_t* __restrict__ Olo)
{
    extern __shared__ char sm[];
    const uint32_t smb = smem_u32(sm);

    const int tid = threadIdx.x;
    const int wid = tid >> 5, lane = tid & 31;
    const int g = lane >> 2, tig = lane & 3;

    const int qt = (gridDim.y - 1) - blockIdx.y;   // heavy tiles first
    const int bh = blockIdx.x;
    const int b  = bh >> 3, h = bh & 7;
    const size_t base = (size_t)b * S_ * C_ + (size_t)h * D_;
    const int q0 = qt * 128;
    const int wr0 = wid * 16;

    const uint16_t* Qhi = QKVhi + base;
    const uint16_t* Qlo = QKVlo + base;
    const uint16_t* Khi = QKVhi + NC + base;
    const uint16_t* Klo = QKVlo + NC + base;
    const uint16_t* Vhi = QKVhi + 2 * NC + base;
    const uint16_t* Vlo = QKVlo + 2 * NC + base;

#pragma unroll
    for (int p = 0; p < 8; p++) {
        const int id = p * 256 + tid;
        const int half = id >> 10;
        const int pl = (id >> 9) & 1;
        const int rl = (id & 511) >> 3;
        const int ch = id & 7;
        const uint32_t dst = smb + (half * 2 + pl) * PLANE +
                             (uint32_t)(rl * FS + ch * 8) * 2;
        const uint16_t* src = (pl ? Qlo : Qhi) +
                              (size_t)(q0 + half * 64 + rl) * C_ + ch * 8;
        cpa16(dst, src);
    }
    CPA_COMMIT();
    CPA_WAIT0();
    __syncthreads();

    uint32_t qh[4][4], ql[4][4];
    {
        const uint32_t areaH = smb + ((wid >= 4) ? 2 * PLANE : 0);
        const int lw = (wid & 3) * 16;
#pragma unroll
        for (int kf = 0; kf < 4; kf++) {
            const uint32_t ae =
                (uint32_t)((lw + (lane & 15)) * FS + kf * 16 +
                           ((lane >> 4) << 3)) * 2;
            ldsm4(qh[kf], areaH + ae);
            ldsm4(ql[kf], areaH + PLANE + ae);
        }
    }
    __syncthreads();

    float acc[8][4];
#pragma unroll
    for (int i = 0; i < 8; i++)
#pragma unroll
        for (int e = 0; e < 4; e++) acc[i][e] = 0.f;
    float m0 = -1e30f, m1 = -1e30f, l0 = 0.f, l1 = 0.f;   // l are lane-partials

    const int r0 = q0 + wr0 + g;
    const int r1 = r0 + 8;
    const int nkt = 2 * qt + 2;

    auto preload = [&](int kt, int buf) {
        const int k0 = kt * 64;
        const uint32_t bb = smb + buf * BUFSZ;
#pragma unroll
        for (int p = 0; p < 8; p++) {
            const int id = p * 256 + tid;
            const int pl = id >> 9;
            const int rl = (id & 511) >> 3;
            const int ch = id & 7;
            const uint32_t dst = bb + pl * PLANE +
                                 (uint32_t)(rl * FS + ch * 8) * 2;
            const uint16_t* src =
                ((pl == 0) ? Khi : (pl == 1) ? Klo : (pl == 2) ? Vhi : Vlo) +
                (size_t)(k0 + rl) * C_ + ch * 8;
            cpa16(dst, src);
        }
    };

    preload(0, 0);
    CPA_COMMIT();

    for (int kt = 0; kt < nkt; kt++) {
        const int k0g = kt * 64;
        CPA_WAIT0();
        __syncthreads();
        if (kt + 1 < nkt) {
            preload(kt + 1, (kt + 1) & 1);
            CPA_COMMIT();
        }

        if (k0g <= q0 + wr0 + 15) {
            const uint32_t kb = smb + (kt & 1) * BUFSZ;

            float s[8][4];
#pragma unroll
            for (int i = 0; i < 8; i++)
#pragma unroll
                for (int e = 0; e < 4; e++) s[i][e] = 0.f;

#pragma unroll
            for (int kf = 0; kf < 4; kf++) {
#pragma unroll
                for (int nfq = 0; nfq < 4; nfq++) {
                    const uint32_t be =
                        (uint32_t)((nfq * 16 + (lane & 7) + ((lane >> 4) << 3)) * FS +
                                   kf * 16 + (((lane >> 3) & 1) << 3)) * 2;
                    uint32_t rh[4], rl_[4];
                    ldsm4(rh, kb + be);
                    ldsm4(rl_, kb + PLANE + be);
                    mma16816(s[2 * nfq], qh[kf], rh);
                    mma16816(s[2 * nfq], qh[kf], rl_);
                    mma16816(s[2 * nfq], ql[kf], rh);
                    mma16816(s[2 * nfq + 1], qh[kf], rh + 2);
                    mma16816(s[2 * nfq + 1], qh[kf], rl_ + 2);
                    mma16816(s[2 * nfq + 1], ql[kf], rh + 2);
                }
            }

            // causal mask (scores already ATT_SCALE-scaled via Q)
            if (k0g + 63 > q0 + wr0) {
#pragma unroll
                for (int nf = 0; nf < 8; nf++) {
                    const int cc = k0g + nf * 8 + tig * 2;
                    if (cc     > r0) s[nf][0] = -1e30f;
                    if (cc + 1 > r0) s[nf][1] = -1e30f;
                    if (cc     > r1) s[nf][2] = -1e30f;
                    if (cc + 1 > r1) s[nf][3] = -1e30f;
                }
            }

            float ml0 = -1e30f, ml1 = -1e30f;
#pragma unroll
            for (int nf = 0; nf < 8; nf++) {
                ml0 = fmaxf(ml0, fmaxf(s[nf][0], s[nf][1]));
                ml1 = fmaxf(ml1, fmaxf(s[nf][2], s[nf][3]));
            }
            ml0 = fmaxf(ml0, __shfl_xor_sync(0xffffffffu, ml0, 1));
            ml0 = fmaxf(ml0, __shfl_xor_sync(0xffffffffu, ml0, 2));
            ml1 = fmaxf(ml1, __shfl_xor_sync(0xffffffffu, ml1, 1));
            ml1 = fmaxf(ml1, __shfl_xor_sync(0xffffffffu, ml1, 2));

            const float mn0 = fmaxf(m0, ml0);
            const float mn1 = fmaxf(m1, ml1);
            const float cr0 = __expf(m0 - mn0);
            const float cr1 = __expf(m1 - mn1);
            m0 = mn0; m1 = mn1;

            float rs0 = 0.f, rs1 = 0.f;
#pragma unroll
            for (int nf = 0; nf < 8; nf++) {
                s[nf][0] = __expf(s[nf][0] - mn0);
                s[nf][1] = __expf(s[nf][1] - mn0);
                s[nf][2] = __expf(s[nf][2] - mn1);
                s[nf][3] = __expf(s[nf][3] - mn1);
                rs0 += s[nf][0] + s[nf][1];
                rs1 += s[nf][2] + s[nf][3];
                acc[nf][0] *= cr0; acc[nf][1] *= cr0;
                acc[nf][2] *= cr1; acc[nf][3] *= cr1;
            }
            // lane-partial l update (no shuffles; cr uniform across quad)
            l0 = l0 * cr0 + rs0;
            l1 = l1 * cr1 + rs1;

#pragma unroll
            for (int kf = 0; kf < 4; kf++) {
                uint32_t aph[4], apl[4];
                split2(s[2 * kf][0],     s[2 * kf][1],     aph[0], apl[0]);
                split2(s[2 * kf][2],     s[2 * kf][3],     aph[1], apl[1]);
                split2(s[2 * kf + 1][0], s[2 * kf + 1][1], aph[2], apl[2]);
                split2(s[2 * kf + 1][2], s[2 * kf + 1][3], aph[3], apl[3]);
#pragma unroll
                for (int nfq = 0; nfq < 4; nfq++) {
                    const uint32_t be =
                        (uint32_t)((kf * 16 + (lane & 7) + (((lane >> 3) & 1) << 3)) * FS +
                                   nfq * 16 + ((lane >> 4) << 3)) * 2;
                    uint32_t vh[4], vl[4];
                    ldsm4t(vh, kb + 2 * PLANE + be);
                    ldsm4t(vl, kb + 3 * PLANE + be);
                    mma16816(acc[2 * nfq], aph, vh);
                    mma16816(acc[2 * nfq], aph, vl);
                    mma16816(acc[2 * nfq], apl, vh);
                    mma16816(acc[2 * nfq + 1], aph, vh + 2);
                    mma16816(acc[2 * nfq + 1], aph, vl + 2);
                    mma16816(acc[2 * nfq + 1], apl, vh + 2);
                }
            }
        }
    }

    // epilogue: quad-reduce lane-partial l, normalize, split, store
    l0 += __shfl_xor_sync(0xffffffffu, l0, 1);
    l0 += __shfl_xor_sync(0xffffffffu, l0, 2);
    l1 += __shfl_xor_sync(0xffffffffu, l1, 1);
    l1 += __shfl_xor_sync(0xffffffffu, l1, 2);
    const float il0 = 1.f / l0;
    const float il1 = 1.f / l1;
#pragma unroll
    for (int nf = 0; nf < 8; nf++) {
        const int col = nf * 8 + tig * 2;
        uint32_t hi, lo;
        split2(acc[nf][0] * il0, acc[nf][1] * il0, hi, lo);
        *(uint32_t*)(Ohi + base + (size_t)r0 * C_ + col) = hi;
        *(uint32_t*)(Olo + base + (size_t)r0 * C_ + col) = lo;
        split2(acc[nf][2] * il1, acc[nf][3] * il1, hi, lo);
        *(uint32_t*)(Ohi + base + (size_t)r1 * C_ + col) = hi;
        *(uint32_t*)(Olo + base + (size_t)r1 * C_ + col) = lo;
    }
}

// ---------------------------------------------------------------------------
// Launcher
// ---------------------------------------------------------------------------
extern "C" void kernel_launch(void* const* d_in, const int* in_sizes, int n_in,
                              void* d_out, int out_size)
{
    (void)in_sizes; (void)n_in; (void)out_size;

    const float* x        = (const float*)d_in[0];
    const float* Wq       = (const float*)d_in[1];
    const float* Wk       = (const float*)d_in[2];
    const float* Wv       = (const float*)d_in[3];
    const float* Wo       = (const float*)d_in[4];
    const float* ln1_w    = (const float*)d_in[5];
    const float* ln1_b    = (const float*)d_in[6];
    const float* ff_ln1_w = (const float*)d_in[7];
    const float* ff_ln1_b = (const float*)d_in[8];
    const float* ff_w1    = (const float*)d_in[9];
    const float* ff_b1    = (const float*)d_in[10];
    const float* ff_ln2_w = (const float*)d_in[11];
    const float* ff_ln2_b = (const float*)d_in[12];
    const float* ff_w2    = (const float*)d_in[13];
    const float* ff_b2    = (const float*)d_in[14];
    const float* ln2_w    = (const float*)d_in[15];
    const float* ln2_b    = (const float*)d_in[16];
    float* out = (float*)d_out;

    float *t0, *xln, *t1;
    uint16_t *xhi, *xlo, *whi, *wlo, *qkvhi, *qkvlo, *atthi, *attlo, *t0hi, *t0lo;
    cudaGetSymbolAddress((void**)&t0,    g_t0);
    cudaGetSymbolAddress((void**)&xln,   g_xln);
    cudaGetSymbolAddress((void**)&t1,    g_t1);
    cudaGetSymbolAddress((void**)&xhi,   g_xhi);
    cudaGetSymbolAddress((void**)&xlo,   g_xlo);
    cudaGetSymbolAddress((void**)&whi,   g_whi);
    cudaGetSymbolAddress((void**)&wlo,   g_wlo);
    cudaGetSymbolAddress((void**)&qkvhi, g_qkvhi);
    cudaGetSymbolAddress((void**)&qkvlo, g_qkvlo);
    cudaGetSymbolAddress((void**)&atthi, g_atthi);
    cudaGetSymbolAddress((void**)&attlo, g_attlo);
    cudaGetSymbolAddress((void**)&t0hi,  g_t0hi);
    cudaGetSymbolAddress((void**)&t0lo,  g_t0lo);

    cudaFuncSetAttribute(flash_k, cudaFuncAttributeMaxDynamicSharedMemorySize,
                         FLASH_SMEM);
    cudaFuncSetAttribute(gemm_tc, cudaFuncAttributeMaxDynamicSharedMemorySize,
                         GEMM_SMEM);

    // Split inputs
    split1_k<<<(int)(NC / 2048), 256>>>(x, xhi, xlo);
    splitw_k<<<dim3((int)(CC / 2048), 1, 6), 256>>>(Wq, Wk, Wv, Wo, ff_w1, ff_w2,
                                                    whi, wlo);

    const dim3 g3(C_ / 128, NTOK / 128, 3);
    const dim3 g1(C_ / 128, NTOK / 128, 1);

    // QKV projections -> split q/k/v; Q scaled by ATT_SCALE (exact, 2^-3)
    gemm_tc<<<g3, 256, GEMM_SMEM>>>(xhi, xlo, whi, wlo,
                                    nullptr, nullptr, qkvhi, qkvlo, ATT_SCALE);

    // Causal flash attention -> split att (LPT grid)
    flash_k<<<dim3(B_ * H_, S_ / 128), 256, FLASH_SMEM>>>(qkvhi, qkvlo,
                                                          atthi, attlo);

    // Output projection -> fp32 t0
    gemm_tc<<<g1, 256, GEMM_SMEM>>>(atthi, attlo, whi + 3 * CC, wlo + 3 * CC,
                                    t0, nullptr, nullptr, nullptr, 1.f);

    // xln = LN1(t0 + x); split = LNff1(xln)
    ln2x_k<<<NTOK, 128>>>(t0, x, ln1_w, ln1_b, xln,
                          ff_ln1_w, ff_ln1_b, t0hi, t0lo);

    // h = LN(x_ln) @ ff_w1 + b1
    gemm_tc<<<g1, 256, GEMM_SMEM>>>(t0hi, t0lo, whi + 4 * CC, wlo + 4 * CC,
                                    t1, ff_b1, nullptr, nullptr, 1.f);

    // h = LN(h) @ ff_w2 + b2
    ln_k<<<NTOK, 128>>>(t1, nullptr, ff_ln2_w, ff_ln2_b, nullptr, t0hi, t0lo);
    gemm_tc<<<g1, 256, GEMM_SMEM>>>(t0hi, t0lo, whi + 5 * CC, wlo + 5 * CC,
                                    t1, ff_b2, nullptr, nullptr, 1.f);

    // out = LN(h + x_ln)
    ln_k<<<NTOK, 128>>>(t1, xln, ln2_w, ln2_b, out, nullptr, nullptr);
}

// round 17
// speedup vs baseline: 1.1654x; 1.0001x over previous
#include <cuda_runtime.h>
#include <cuda_bf16.h>
#include <math.h>
#include <stdint.h>

#define B_ 4
#define S_ 2048
#define C_ 512
#define H_ 8
#define D_ 64
#define NTOK (B_ * S_)
#define ATT_SCALE 0.125f
#define LOG2E 1.4426950408889634f
#define LN_EPS 1e-5f
#define NC ((size_t)NTOK * C_)
#define CC ((size_t)C_ * C_)

// ---------------------------------------------------------------------------
// Scratch buffers
// ---------------------------------------------------------------------------
__device__ float g_t0 [NC];
__device__ float g_xln[NC];
__device__ float g_t1 [NC];

__device__ uint16_t g_xhi [NC],     g_xlo [NC];
__device__ uint16_t g_whi [6 * CC], g_wlo [6 * CC];
__device__ uint16_t g_qkvhi[3 * NC], g_qkvlo[3 * NC];
__device__ uint16_t g_atthi[NC],    g_attlo[NC];
__device__ uint16_t g_t0hi[NC],     g_t0lo[NC];

// ---------------------------------------------------------------------------
// Helpers
// ---------------------------------------------------------------------------
__device__ __forceinline__ uint32_t smem_u32(const void* p) {
    uint32_t a;
    asm("{ .reg .u64 t; cvta.to.shared.u64 t, %1; cvt.u32.u64 %0, t; }"
        : "=r"(a) : "l"(p));
    return a;
}
__device__ __forceinline__ void ldsm4(uint32_t* r, uint32_t addr) {
    asm volatile("ldmatrix.sync.aligned.m8n8.x4.shared.b16 {%0,%1,%2,%3}, [%4];"
                 : "=r"(r[0]), "=r"(r[1]), "=r"(r[2]), "=r"(r[3]) : "r"(addr));
}
__device__ __forceinline__ void ldsm4t(uint32_t* r, uint32_t addr) {
    asm volatile("ldmatrix.sync.aligned.m8n8.x4.trans.shared.b16 {%0,%1,%2,%3}, [%4];"
                 : "=r"(r[0]), "=r"(r[1]), "=r"(r[2]), "=r"(r[3]) : "r"(addr));
}
__device__ __forceinline__ void mma16816(float* c, const uint32_t* a, const uint32_t* b) {
    asm volatile(
        "mma.sync.aligned.m16n8k16.row.col.f32.bf16.bf16.f32 "
        "{%0,%1,%2,%3},{%4,%5,%6,%7},{%8,%9},{%0,%1,%2,%3};"
        : "+f"(c[0]), "+f"(c[1]), "+f"(c[2]), "+f"(c[3])
        : "r"(a[0]), "r"(a[1]), "r"(a[2]), "r"(a[3]), "r"(b[0]), "r"(b[1]));
}
__device__ __forceinline__ void cpa16(uint32_t dst, const void* src) {
    asm volatile("cp.async.cg.shared.global [%0], [%1], 16;" :: "r"(dst), "l"(src));
}
#define CPA_COMMIT() asm volatile("cp.async.commit_group;")
#define CPA_WAIT0()  asm volatile("cp.async.wait_group 0;")
#define CPA_WAIT1()  asm volatile("cp.async.wait_group 1;")

__device__ __forceinline__ float ex2(float x) {
    float r;
    asm("ex2.approx.f32 %0, %1;" : "=f"(r) : "f"(x));
    return r;
}

__device__ __forceinline__ uint16_t f2bf(float x) {
    __nv_bfloat16 b = __float2bfloat16(x);
    return *(uint16_t*)&b;
}
__device__ __forceinline__ float bf2f(uint16_t u) {
    __nv_bfloat16 b = *(__nv_bfloat16*)&u;
    return __bfloat162float(b);
}
__device__ __forceinline__ void split2(float x0, float x1, uint32_t& hi, uint32_t& lo) {
    uint16_t h0 = f2bf(x0), h1 = f2bf(x1);
    uint16_t l0 = f2bf(x0 - bf2f(h0)), l1 = f2bf(x1 - bf2f(h1));
    hi = (uint32_t)h0 | ((uint32_t)h1 << 16);
    lo = (uint32_t)l0 | ((uint32_t)l1 << 16);
}

// ---------------------------------------------------------------------------
// Split kernels
// ---------------------------------------------------------------------------
__global__ __launch_bounds__(256) void split1_k(
    const float* __restrict__ in, uint16_t* __restrict__ hi,
    uint16_t* __restrict__ lo)
{
    const size_t i = ((size_t)blockIdx.x * 256 + threadIdx.x) * 8;
    float4 a = *(const float4*)(in + i);
    float4 b = *(const float4*)(in + i + 4);
    uint32_t h0, l0, h1, l1, h2, l2, h3, l3;
    split2(a.x, a.y, h0, l0); split2(a.z, a.w, h1, l1);
    split2(b.x, b.y, h2, l2); split2(b.z, b.w, h3, l3);
    *(uint4*)(hi + i) = make_uint4(h0, h1, h2, h3);
    *(uint4*)(lo + i) = make_uint4(l0, l1, l2, l3);
}

__global__ __launch_bounds__(256) void splitw_k(
    const float* __restrict__ w0, const float* __restrict__ w1,
    const float* __restrict__ w2, const float* __restrict__ w3,
    const float* __restrict__ w4, const float* __restrict__ w5,
    uint16_t* __restrict__ hi, uint16_t* __restrict__ lo)
{
    const int z = blockIdx.z;
    const float* w = (z == 0) ? w0 : (z == 1) ? w1 : (z == 2) ? w2 :
                     (z == 3) ? w3 : (z == 4) ? w4 : w5;
    const size_t j = ((size_t)blockIdx.x * 256 + threadIdx.x) * 8;
    const size_t o = (size_t)z * CC + j;
    float4 a = *(const float4*)(w + j);
    float4 b = *(const float4*)(w + j + 4);
    uint32_t h0, l0, h1, l1, h2, l2, h3, l3;
    split2(a.x, a.y, h0, l0); split2(a.z, a.w, h1, l1);
    split2(b.x, b.y, h2, l2); split2(b.z, b.w, h3, l3);
    *(uint4*)(hi + o) = make_uint4(h0, h1, h2, h3);
    *(uint4*)(lo + o) = make_uint4(l0, l1, l2, l3);
}

// ---------------------------------------------------------------------------
// bf16x3 GEMM: 128x128 tile, BK=32, 256 threads, 3-stage cp.async ring.
// oscale multiplies the split output for blockIdx.z==0 (ATT_SCALE*log2e
// folded into Q so flash works in the log2 domain).
// ---------------------------------------------------------------------------
#define GSA 40
#define GSB 136
#define APL 10240
#define BPL 8704
#define STG 37888
#define GEMM_SMEM (3 * STG)

__global__ __launch_bounds__(256) void gemm_tc(
    const uint16_t* __restrict__ Ahi, const uint16_t* __restrict__ Alo,
    const uint16_t* __restrict__ Whi, const uint16_t* __restrict__ Wlo,
    float* __restrict__ Cf, const float* __restrict__ bias,
    uint16_t* __restrict__ Chi, uint16_t* __restrict__ Clo,
    float oscale)
{
    extern __shared__ char sm[];
    const uint32_t smb = smem_u32(sm);
    const int tid = threadIdx.x;
    const int wid = tid >> 5, lane = tid & 31;
    const int g = lane >> 2, tig = lane & 3;
    const int wm = wid >> 2, wn = wid & 3;
    const int n0 = blockIdx.x * 128, m0 = blockIdx.y * 128;
    const uint16_t* Wh = Whi + (size_t)blockIdx.z * CC;
    const uint16_t* Wl = Wlo + (size_t)blockIdx.z * CC;
    const size_t zO = (size_t)blockIdx.z * NC;
    const float sc = (blockIdx.z == 0) ? oscale : 1.f;

    float c[4][4][4];
#pragma unroll
    for (int i = 0; i < 4; i++)
#pragma unroll
        for (int j = 0; j < 4; j++)
#pragma unroll
            for (int e = 0; e < 4; e++) c[i][j][e] = 0.f;

    auto preload = [&](int chunk, int buf) {
        const uint32_t sb = smb + (uint32_t)buf * STG;
        const int k0 = chunk * 32;
#pragma unroll
        for (int rep = 0; rep < 2; rep++) {
            const int cc = tid + rep * 256;
            {
                const int row = cc >> 2, kc = cc & 3;
                const uint32_t d = sb + row * 80 + kc * 16;
                const size_t so = (size_t)(m0 + row) * C_ + k0 + kc * 8;
                cpa16(d, Ahi + so);
                cpa16(d + APL, Alo + so);
            }
            {
                const int row = cc >> 4, nc = cc & 15;
                const uint32_t d = sb + 2 * APL + row * 272 + nc * 16;
                const size_t so = (size_t)(k0 + row) * C_ + n0 + nc * 8;
                cpa16(d, Wh + so);
                cpa16(d + BPL, Wl + so);
            }
        }
    };

    auto compute = [&](int buf) {
        const uint32_t sb = smb + (uint32_t)buf * STG;
#pragma unroll
        for (int kk = 0; kk < 32; kk += 16) {
            uint32_t ah[4][4], al[4][4];
#pragma unroll
            for (int mf = 0; mf < 4; mf++) {
                const uint32_t ae =
                    (uint32_t)((wm * 64 + mf * 16 + (lane & 15)) * GSA +
                               kk + ((lane >> 4) << 3)) * 2;
                ldsm4(ah[mf], sb + ae);
                ldsm4(al[mf], sb + APL + ae);
            }
            uint32_t bh[4][2], bl[4][2];
#pragma unroll
            for (int nfp = 0; nfp < 2; nfp++) {
                const uint32_t be =
                    (uint32_t)((kk + (lane & 7) + (((lane >> 3) & 1) << 3)) * GSB +
                               wn * 32 + nfp * 16 + ((lane >> 4) << 3)) * 2;
                uint32_t r[4];
                ldsm4t(r, sb + 2 * APL + be);
                bh[nfp * 2][0] = r[0]; bh[nfp * 2][1] = r[1];
                bh[nfp * 2 + 1][0] = r[2]; bh[nfp * 2 + 1][1] = r[3];
                ldsm4t(r, sb + 2 * APL + BPL + be);
                bl[nfp * 2][0] = r[0]; bl[nfp * 2][1] = r[1];
                bl[nfp * 2 + 1][0] = r[2]; bl[nfp * 2 + 1][1] = r[3];
            }
#pragma unroll
            for (int mf = 0; mf < 4; mf++)
#pragma unroll
                for (int nf = 0; nf < 4; nf++) {
                    mma16816(c[mf][nf], ah[mf], bh[nf]);
                    mma16816(c[mf][nf], ah[mf], bl[nf]);
                    mma16816(c[mf][nf], al[mf], bh[nf]);
                }
        }
    };

    preload(0, 0);
    CPA_COMMIT();
    preload(1, 1);
    CPA_COMMIT();
    for (int ch = 0; ch < 16; ch++) {
        if (ch < 15) CPA_WAIT1(); else CPA_WAIT0();
        __syncthreads();
        if (ch + 2 < 16) {
            preload(ch + 2, (ch + 2) % 3);
            CPA_COMMIT();
        }
        compute(ch % 3);
    }

#pragma unroll
    for (int mf = 0; mf < 4; mf++) {
        const int row0 = m0 + wm * 64 + mf * 16 + g;
        const int row1 = row0 + 8;
#pragma unroll
        for (int nf = 0; nf < 4; nf++) {
            const int col = n0 + wn * 32 + nf * 8 + tig * 2;
            if (Cf) {
                float bx = 0.f, by = 0.f;
                if (bias) { bx = bias[col]; by = bias[col + 1]; }
                *(float2*)(Cf + (size_t)row0 * C_ + col) =
                    make_float2(c[mf][nf][0] + bx, c[mf][nf][1] + by);
                *(float2*)(Cf + (size_t)row1 * C_ + col) =
                    make_float2(c[mf][nf][2] + bx, c[mf][nf][3] + by);
            } else {
                uint32_t hi, lo;
                split2(c[mf][nf][0] * sc, c[mf][nf][1] * sc, hi, lo);
                *(uint32_t*)(Chi + zO + (size_t)row0 * C_ + col) = hi;
                *(uint32_t*)(Clo + zO + (size_t)row0 * C_ + col) = lo;
                split2(c[mf][nf][2] * sc, c[mf][nf][3] * sc, hi, lo);
                *(uint32_t*)(Chi + zO + (size_t)row1 * C_ + col) = hi;
                *(uint32_t*)(Clo + zO + (size_t)row1 * C_ + col) = lo;
            }
        }
    }
}

// ---------------------------------------------------------------------------
// LayerNorm
// ---------------------------------------------------------------------------
__device__ __forceinline__ void ln_row_stats(float4 v, int t, float& mean,
                                             float& inv, float* rs, float* rs2)
{
    float s  = v.x + v.y + v.z + v.w;
    float s2 = v.x * v.x + v.y * v.y + v.z * v.z + v.w * v.w;
#pragma unroll
    for (int o = 16; o; o >>= 1) {
        s  += __shfl_xor_sync(0xffffffffu, s,  o);
        s2 += __shfl_xor_sync(0xffffffffu, s2, o);
    }
    const int wid = t >> 5;
    if ((t & 31) == 0) { rs[wid] = s; rs2[wid] = s2; }
    __syncthreads();
    float S  = rs[0]  + rs[1]  + rs[2]  + rs[3];
    float S2 = rs2[0] + rs2[1] + rs2[2] + rs2[3];
    mean = S * (1.f / C_);
    const float var = S2 * (1.f / C_) - mean * mean;
    inv = rsqrtf(var + LN_EPS);
}

__global__ __launch_bounds__(128) void ln_k(
    const float* __restrict__ in, const float* __restrict__ res,
    const float* __restrict__ w, const float* __restrict__ b,
    float* __restrict__ out, uint16_t* __restrict__ ohi,
    uint16_t* __restrict__ olo)
{
    const int row = blockIdx.x;
    const int t = threadIdx.x;
    __shared__ float rs[4], rs2[4];

    float4 v = *(const float4*)(in + (size_t)row * C_ + t * 4);
    if (res) {
        float4 r = *(const float4*)(res + (size_t)row * C_ + t * 4);
        v.x += r.x; v.y += r.y; v.z += r.z; v.w += r.w;
    }
    float mean, inv;
    ln_row_stats(v, t, mean, inv, rs, rs2);

    float4 wv = *(const float4*)(w + t * 4);
    float4 bv = *(const float4*)(b + t * 4);
    float4 o;
    o.x = (v.x - mean) * inv * wv.x + bv.x;
    o.y = (v.y - mean) * inv * wv.y + bv.y;
    o.z = (v.z - mean) * inv * wv.z + bv.z;
    o.w = (v.w - mean) * inv * wv.w + bv.w;
    if (out)
        *(float4*)(out + (size_t)row * C_ + t * 4) = o;
    if (ohi) {
        uint32_t h0, l0, h1, l1;
        split2(o.x, o.y, h0, l0);
        split2(o.z, o.w, h1, l1);
        *(uint2*)(ohi + (size_t)row * C_ + t * 4) = make_uint2(h0, h1);
        *(uint2*)(olo + (size_t)row * C_ + t * 4) = make_uint2(l0, l1);
    }
}

// Fused double-LN: xln = LN1(in+res); split = LN2(xln).
__global__ __launch_bounds__(128) void ln2x_k(
    const float* __restrict__ in, const float* __restrict__ res,
    const float* __restrict__ w1, const float* __restrict__ b1,
    float* __restrict__ xln_out,
    const float* __restrict__ w2, const float* __restrict__ b2,
    uint16_t* __restrict__ ohi, uint16_t* __restrict__ olo)
{
    const int row = blockIdx.x;
    const int t = threadIdx.x;
    __shared__ float rs[4], rs2[4];

    float4 v = *(const float4*)(in + (size_t)row * C_ + t * 4);
    float4 r = *(const float4*)(res + (size_t)row * C_ + t * 4);
    v.x += r.x; v.y += r.y; v.z += r.z; v.w += r.w;

    float mean, inv;
    ln_row_stats(v, t, mean, inv, rs, rs2);

    float4 w1v = *(const float4*)(w1 + t * 4);
    float4 b1v = *(const float4*)(b1 + t * 4);
    float4 x1;
    x1.x = (v.x - mean) * inv * w1v.x + b1v.x;
    x1.y = (v.y - mean) * inv * w1v.y + b1v.y;
    x1.z = (v.z - mean) * inv * w1v.z + b1v.z;
    x1.w = (v.w - mean) * inv * w1v.w + b1v.w;
    *(float4*)(xln_out + (size_t)row * C_ + t * 4) = x1;

    __syncthreads();
    float mean2, inv2;
    ln_row_stats(x1, t, mean2, inv2, rs, rs2);

    float4 w2v = *(const float4*)(w2 + t * 4);
    float4 b2v = *(const float4*)(b2 + t * 4);
    float4 o;
    o.x = (x1.x - mean2) * inv2 * w2v.x + b2v.x;
    o.y = (x1.y - mean2) * inv2 * w2v.y + b2v.y;
    o.z = (x1.z - mean2) * inv2 * w2v.z + b2v.z;
    o.w = (x1.w - mean2) * inv2 * w2v.w + b2v.w;
    uint32_t h0, l0, h1, l1;
    split2(o.x, o.y, h0, l0);
    split2(o.z, o.w, h1, l1);
    *(uint2*)(ohi + (size_t)row * C_ + t * 4) = make_uint2(h0, h1);
    *(uint2*)(olo + (size_t)row * C_ + t * 4) = make_uint2(l0, l1);
}

// ---------------------------------------------------------------------------
// FA2-style flash attention, base-2 softmax. Grid = (bh, qt), LPT order.
// Q pre-scaled by ATT_SCALE*log2e -> scores in log2 domain, exp = ex2.
// Row-sum l lane-partial, quad-reduced in the epilogue.
// ---------------------------------------------------------------------------
#define FS 72
#define PLANE 9216
#define BUFSZ (4 * PLANE)
#define FLASH_SMEM (2 * BUFSZ)

__global__ __launch_bounds__(256, 1) void flash_k(
    const uint16_t* __restrict__ QKVhi, const uint16_t* __restrict__ QKVlo,
    uint16_t* __restrict__ Ohi, uint16_t* __restrict__ Olo)
{
    extern __shared__ char sm[];
    const uint32_t smb = smem_u32(sm);

    const int tid = threadIdx.x;
    const int wid = tid >> 5, lane = tid & 31;
    const int g = lane >> 2, tig = lane & 3;

    const int qt = (gridDim.y - 1) - blockIdx.y;
    const int bh = blockIdx.x;
    const int b  = bh >> 3, h = bh & 7;
    const size_t base = (size_t)b * S_ * C_ + (size_t)h * D_;
    const int q0 = qt * 128;
    const int wr0 = wid * 16;

    const uint16_t* Qhi = QKVhi + base;
    const uint16_t* Qlo = QKVlo + base;
    const uint16_t* Khi = QKVhi + NC + base;
    const uint16_t* Klo = QKVlo + NC + base;
    const uint16_t* Vhi = QKVhi + 2 * NC + base;
    const uint16_t* Vlo = QKVlo + 2 * NC + base;

#pragma unroll
    for (int p = 0; p < 8; p++) {
        const int id = p * 256 + tid;
        const int half = id >> 10;
        const int pl = (id >> 9) & 1;
        const int rl = (id & 511) >> 3;
        const int ch = id & 7;
        const uint32_t dst = smb + (half * 2 + pl) * PLANE +
                             (uint32_t)(rl * FS + ch * 8) * 2;
        const uint16_t* src = (pl ? Qlo : Qhi) +
                              (size_t)(q0 + half * 64 + rl) * C_ + ch * 8;
        cpa16(dst, src);
    }
    CPA_COMMIT();
    CPA_WAIT0();
    __syncthreads();

    uint32_t qh[4][4], ql[4][4];
    {
        const uint32_t areaH = smb + ((wid >= 4) ? 2 * PLANE : 0);
        const int lw = (wid & 3) * 16;
#pragma unroll
        for (int kf = 0; kf < 4; kf++) {
            const uint32_t ae =
                (uint32_t)((lw + (lane & 15)) * FS + kf * 16 +
                           ((lane >> 4) << 3)) * 2;
            ldsm4(qh[kf], areaH + ae);
            ldsm4(ql[kf], areaH + PLANE + ae);
        }
    }
    __syncthreads();

    float acc[8][4];
#pragma unroll
    for (int i = 0; i < 8; i++)
#pragma unroll
        for (int e = 0; e < 4; e++) acc[i][e] = 0.f;
    float m0 = -1e30f, m1 = -1e30f, l0 = 0.f, l1 = 0.f;

    const int r0 = q0 + wr0 + g;
    const int r1 = r0 + 8;
    const int nkt = 2 * qt + 2;

    auto preload = [&](int kt, int buf) {
        const int k0 = kt * 64;
        const uint32_t bb = smb + buf * BUFSZ;
#pragma unroll
        for (int p = 0; p < 8; p++) {
            const int id = p * 256 + tid;
            const int pl = id >> 9;
            const int rl = (id & 511) >> 3;
            const int ch = id & 7;
            const uint32_t dst = bb + pl * PLANE +
                                 (uint32_t)(rl * FS + ch * 8) * 2;
            const uint16_t* src =
                ((pl == 0) ? Khi : (pl == 1) ? Klo : (pl == 2) ? Vhi : Vlo) +
                (size_t)(k0 + rl) * C_ + ch * 8;
            cpa16(dst, src);
        }
    };

    preload(0, 0);
    CPA_COMMIT();

    for (int kt = 0; kt < nkt; kt++) {
        const int k0g = kt * 64;
        CPA_WAIT0();
        __syncthreads();
        if (kt + 1 < nkt) {
            preload(kt + 1, (kt + 1) & 1);
            CPA_COMMIT();
        }

        if (k0g <= q0 + wr0 + 15) {
            const uint32_t kb = smb + (kt & 1) * BUFSZ;

            float s[8][4];
#pragma unroll
            for (int i = 0; i < 8; i++)
#pragma unroll
                for (int e = 0; e < 4; e++) s[i][e] = 0.f;

#pragma unroll
            for (int kf = 0; kf < 4; kf++) {
#pragma unroll
                for (int nfq = 0; nfq < 4; nfq++) {
                    const uint32_t be =
                        (uint32_t)((nfq * 16 + (lane & 7) + ((lane >> 4) << 3)) * FS +
                                   kf * 16 + (((lane >> 3) & 1) << 3)) * 2;
                    uint32_t rh[4], rl_[4];
                    ldsm4(rh, kb + be);
                    ldsm4(rl_, kb + PLANE + be);
                    mma16816(s[2 * nfq], qh[kf], rh);
                    mma16816(s[2 * nfq], qh[kf], rl_);
                    mma16816(s[2 * nfq], ql[kf], rh);
                    mma16816(s[2 * nfq + 1], qh[kf], rh + 2);
                    mma16816(s[2 * nfq + 1], qh[kf], rl_ + 2);
                    mma16816(s[2 * nfq + 1], ql[kf], rh + 2);
                }
            }

            // causal mask (scores already scaled into log2 domain via Q)
            if (k0g + 63 > q0 + wr0) {
#pragma unroll
                for (int nf = 0; nf < 8; nf++) {
                    const int cc = k0g + nf * 8 + tig * 2;
                    if (cc     > r0) s[nf][0] = -1e30f;
                    if (cc + 1 > r0) s[nf][1] = -1e30f;
                    if (cc     > r1) s[nf][2] = -1e30f;
                    if (cc + 1 > r1) s[nf][3] = -1e30f;
                }
            }

            float ml0 = -1e30f, ml1 = -1e30f;
#pragma unroll
            for (int nf = 0; nf < 8; nf++) {
                ml0 = fmaxf(ml0, fmaxf(s[nf][0], s[nf][1]));
                ml1 = fmaxf(ml1, fmaxf(s[nf][2], s[nf][3]));
            }
            ml0 = fmaxf(ml0, __shfl_xor_sync(0xffffffffu, ml0, 1));
            ml0 = fmaxf(ml0, __shfl_xor_sync(0xffffffffu, ml0, 2));
            ml1 = fmaxf(ml1, __shfl_xor_sync(0xffffffffu, ml1, 1));
            ml1 = fmaxf(ml1, __shfl_xor_sync(0xffffffffu, ml1, 2));

            const float mn0 = fmaxf(m0, ml0);
            const float mn1 = fmaxf(m1, ml1);
            const float cr0 = ex2(m0 - mn0);
            const float cr1 = ex2(m1 - mn1);
            m0 = mn0; m1 = mn1;

            float rs0 = 0.f, rs1 = 0.f;
#pragma unroll
            for (int nf = 0; nf < 8; nf++) {
                s[nf][0] = ex2(s[nf][0] - mn0);
                s[nf][1] = ex2(s[nf][1] - mn0);
                s[nf][2] = ex2(s[nf][2] - mn1);
                s[nf][3] = ex2(s[nf][3] - mn1);
                rs0 += s[nf][0] + s[nf][1];
                rs1 += s[nf][2] + s[nf][3];
                acc[nf][0] *= cr0; acc[nf][1] *= cr0;
                acc[nf][2] *= cr1; acc[nf][3] *= cr1;
            }
            l0 = l0 * cr0 + rs0;
            l1 = l1 * cr1 + rs1;

#pragma unroll
            for (int kf = 0; kf < 4; kf++) {
                uint32_t aph[4], apl[4];
                split2(s[2 * kf][0],     s[2 * kf][1],     aph[0], apl[0]);
                split2(s[2 * kf][2],     s[2 * kf][3],     aph[1], apl[1]);
                split2(s[2 * kf + 1][0], s[2 * kf + 1][1], aph[2], apl[2]);
                split2(s[2 * kf + 1][2], s[2 * kf + 1][3], aph[3], apl[3]);
#pragma unroll
                for (int nfq = 0; nfq < 4; nfq++) {
                    const uint32_t be =
                        (uint32_t)((kf * 16 + (lane & 7) + (((lane >> 3) & 1) << 3)) * FS +
                                   nfq * 16 + ((lane >> 4) << 3)) * 2;
                    uint32_t vh[4], vl[4];
                    ldsm4t(vh, kb + 2 * PLANE + be);
                    ldsm4t(vl, kb + 3 * PLANE + be);
                    mma16816(acc[2 * nfq], aph, vh);
                    mma16816(acc[2 * nfq], aph, vl);
                    mma16816(acc[2 * nfq], apl, vh);
                    mma16816(acc[2 * nfq + 1], aph, vh + 2);
                    mma16816(acc[2 * nfq + 1], aph, vl + 2);
                    mma16816(acc[2 * nfq + 1], apl, vh + 2);
                }
            }
        }
    }

    l0 += __shfl_xor_sync(0xffffffffu, l0, 1);
    l0 += __shfl_xor_sync(0xffffffffu, l0, 2);
    l1 += __shfl_xor_sync(0xffffffffu, l1, 1);
    l1 += __shfl_xor_sync(0xffffffffu, l1, 2);
    const float il0 = 1.f / l0;
    const float il1 = 1.f / l1;
#pragma unroll
    for (int nf = 0; nf < 8; nf++) {
        const int col = nf * 8 + tig * 2;
        uint32_t hi, lo;
        split2(acc[nf][0] * il0, acc[nf][1] * il0, hi, lo);
        *(uint32_t*)(Ohi + base + (size_t)r0 * C_ + col) = hi;
        *(uint32_t*)(Olo + base + (size_t)r0 * C_ + col) = lo;
        split2(acc[nf][2] * il1, acc[nf][3] * il1, hi, lo);
        *(uint32_t*)(Ohi + base + (size_t)r1 * C_ + col) = hi;
        *(uint32_t*)(Olo + base + (size_t)r1 * C_ + col) = lo;
    }
}

// ---------------------------------------------------------------------------
// Launcher
// ---------------------------------------------------------------------------
extern "C" void kernel_launch(void* const* d_in, const int* in_sizes, int n_in,
                              void* d_out, int out_size)
{
    (void)in_sizes; (void)n_in; (void)out_size;

    const float* x        = (const float*)d_in[0];
    const float* Wq       = (const float*)d_in[1];
    const float* Wk       = (const float*)d_in[2];
    const float* Wv       = (const float*)d_in[3];
    const float* Wo       = (const float*)d_in[4];
    const float* ln1_w    = (const float*)d_in[5];
    const float* ln1_b    = (const float*)d_in[6];
    const float* ff_ln1_w = (const float*)d_in[7];
    const float* ff_ln1_b = (const float*)d_in[8];
    const float* ff_w1    = (const float*)d_in[9];
    const float* ff_b1    = (const float*)d_in[10];
    const float* ff_ln2_w = (const float*)d_in[11];
    const float* ff_ln2_b = (const float*)d_in[12];
    const float* ff_w2    = (const float*)d_in[13];
    const float* ff_b2    = (const float*)d_in[14];
    const float* ln2_w    = (const float*)d_in[15];
    const float* ln2_b    = (const float*)d_in[16];
    float* out = (float*)d_out;

    float *t0, *xln, *t1;
    uint16_t *xhi, *xlo, *whi, *wlo, *qkvhi, *qkvlo, *atthi, *attlo, *t0hi, *t0lo;
    cudaGetSymbolAddress((void**)&t0,    g_t0);
    cudaGetSymbolAddress((void**)&xln,   g_xln);
    cudaGetSymbolAddress((void**)&t1,    g_t1);
    cudaGetSymbolAddress((void**)&xhi,   g_xhi);
    cudaGetSymbolAddress((void**)&xlo,   g_xlo);
    cudaGetSymbolAddress((void**)&whi,   g_whi);
    cudaGetSymbolAddress((void**)&wlo,   g_wlo);
    cudaGetSymbolAddress((void**)&qkvhi, g_qkvhi);
    cudaGetSymbolAddress((void**)&qkvlo, g_qkvlo);
    cudaGetSymbolAddress((void**)&atthi, g_atthi);
    cudaGetSymbolAddress((void**)&attlo, g_attlo);
    cudaGetSymbolAddress((void**)&t0hi,  g_t0hi);
    cudaGetSymbolAddress((void**)&t0lo,  g_t0lo);

    cudaFuncSetAttribute(flash_k, cudaFuncAttributeMaxDynamicSharedMemorySize,
                         FLASH_SMEM);
    cudaFuncSetAttribute(gemm_tc, cudaFuncAttributeMaxDynamicSharedMemorySize,
                         GEMM_SMEM);

    // Split inputs
    split1_k<<<(int)(NC / 2048), 256>>>(x, xhi, xlo);
    splitw_k<<<dim3((int)(CC / 2048), 1, 6), 256>>>(Wq, Wk, Wv, Wo, ff_w1, ff_w2,
                                                    whi, wlo);

    const dim3 g3(C_ / 128, NTOK / 128, 3);
    const dim3 g1(C_ / 128, NTOK / 128, 1);

    // QKV projections; Q scaled by ATT_SCALE*log2e (base-2 softmax domain)
    gemm_tc<<<g3, 256, GEMM_SMEM>>>(xhi, xlo, whi, wlo,
                                    nullptr, nullptr, qkvhi, qkvlo,
                                    ATT_SCALE * LOG2E);

    // Causal flash attention -> split att (LPT grid)
    flash_k<<<dim3(B_ * H_, S_ / 128), 256, FLASH_SMEM>>>(qkvhi, qkvlo,
                                                          atthi, attlo);

    // Output projection -> fp32 t0
    gemm_tc<<<g1, 256, GEMM_SMEM>>>(atthi, attlo, whi + 3 * CC, wlo + 3 * CC,
                                    t0, nullptr, nullptr, nullptr, 1.f);

    // xln = LN1(t0 + x); split = LNff1(xln)
    ln2x_k<<<NTOK, 128>>>(t0, x, ln1_w, ln1_b, xln,
                          ff_ln1_w, ff_ln1_b, t0hi, t0lo);

    // h = LN(x_ln) @ ff_w1 + b1
    gemm_tc<<<g1, 256, GEMM_SMEM>>>(t0hi, t0lo, whi + 4 * CC, wlo + 4 * CC,
                                    t1, ff_b1, nullptr, nullptr, 1.f);

    // h = LN(h) @ ff_w2 + b2
    ln_k<<<NTOK, 128>>>(t1, nullptr, ff_ln2_w, ff_ln2_b, nullptr, t0hi, t0lo);
    gemm_tc<<<g1, 256, GEMM_SMEM>>>(t0hi, t0lo, whi + 5 * CC, wlo + 5 * CC,
                                    t1, ff_b2, nullptr, nullptr, 1.f);

    // out = LN(h + x_ln)
    ln_k<<<NTOK, 128>>>(t1, xln, ln2_w, ln2_b, out, nullptr, nullptr);
}